// round 10
// baseline (speedup 1.0000x reference)
#include <cuda_runtime.h>
#include <cuda_fp16.h>
#include <mma.h>
#include <cstdint>

using namespace nvcuda;

#define EPS 1e-5f

// Scratch (no cudaMalloc allowed).
__device__ __align__(16) float    g_zf[64 * 256 * 14 * 14];     // 12.8 MB
__device__ __align__(16) float    g_xf[64 * 256 * 30 * 30];     // 59 MB
__device__ __align__(16) uint32_t g_zp[64 * 256 * 16 * 16];     // packed z (fp16 hi|lo)
__device__ __align__(16) uint32_t g_xp[64 * 256 * 32 * 32];     // packed x (fp16 hi|lo)
__device__ __align__(16) __half   g_wz[256 * 2304];             // fp16 weights z
__device__ __align__(16) __half   g_wx[256 * 2304];             // fp16 weights x

__device__ __forceinline__ uint32_t prmt(uint32_t a, uint32_t b, uint32_t sel) {
    uint32_t r;
    asm("prmt.b32 %0, %1, %2, %3;" : "=r"(r) : "r"(a), "r"(b), "r"(sel));
    return r;
}

__device__ __forceinline__ uint32_t smem_u32(const void* p) {
    uint32_t a;
    asm("{ .reg .u64 t; cvta.to.shared.u64 t, %1; cvt.u32.u64 %0, t; }"
        : "=r"(a) : "l"(p));
    return a;
}

#define CP_ASYNC16(dst, src) \
    asm volatile("cp.async.cg.shared.global [%0], [%1], 16;" \
        :: "r"(dst), "l"(src) : "memory")
#define CP_COMMIT() asm volatile("cp.async.commit_group;" ::: "memory")
#define CP_WAIT0()  asm volatile("cp.async.wait_group 0;" ::: "memory")

// fp16 2-split pack: u32 = half(v) | half(v - half(v)) << 16
__device__ __forceinline__ uint32_t pack_h2(float v) {
    __half h = __float2half_rn(v);
    __half l = __float2half_rn(v - __half2float(h));
    return (uint32_t)__half_as_ushort(h) |
           ((uint32_t)__half_as_ushort(l) << 16);
}

// ---- pack inputs: fp32 -> u32 (fp16 hi | fp16 lo<<16) ----
__global__ void pack_in_kernel(const float4* __restrict__ src,
                               uint4* __restrict__ dst, int n4)
{
    int i = blockIdx.x * blockDim.x + threadIdx.x;
    if (i >= n4) return;
    float4 v = __ldg(src + i);
    dst[i] = make_uint4(pack_h2(v.x), pack_h2(v.y), pack_h2(v.z), pack_h2(v.w));
}

// ---- pack weights: fp32 -> single fp16 plane ----
__global__ void pack_w_kernel(const float4* __restrict__ src,
                              uint2* __restrict__ dst, int n4)
{
    int i = blockIdx.x * blockDim.x + threadIdx.x;
    if (i >= n4) return;
    float4 v = __ldg(src + i);
    __half2 h01 = __floats2half2_rn(v.x, v.y);
    __half2 h23 = __floats2half2_rn(v.z, v.w);
    dst[i] = make_uint2(*reinterpret_cast<uint32_t*>(&h01),
                        *reinterpret_cast<uint32_t*>(&h23));
}

// ===========================================================================
// Implicit-GEMM 3x3 conv + fused BN, fp16 wmma 2-split.
//   w*x ~= wh*xh + wh*xl  (weights single fp16, inputs split hi/lo)
// BM=256, BN=64, BK=64, 256 threads, warp tile 64x32, 2 CTAs/SM.
// ===========================================================================
template <int OH, int OW, int IH, int IW>
__global__ __launch_bounds__(256, 2)
void conv3x3_bn_wmma(const uint32_t* __restrict__ xp,   // packed input (hi|lo)
                     const __half* __restrict__ whalf,  // fp16 weights [256,2304]
                     const float* __restrict__ gamma,
                     const float* __restrict__ beta,
                     const float* __restrict__ mean,
                     const float* __restrict__ var,
                     float* __restrict__ out)           // [B,256,OH,OW]
{
    constexpr int C = 256, K = C * 9;
    constexpr int BM = 256, BN = 64, BK = 64;
    constexpr int NCH = K / BK;                 // 36
    constexpr int OHW = OH * OW;
    constexpr int LDA = 72;                     // fp16 elems/row (144 B)
    constexpr int LDC = 68;
    constexpr uint32_t A_T = BM * LDA * 2;      // 36864 (single plane)
    constexpr uint32_t B_T = BN * LDA * 2;      // 9216
    constexpr uint32_t OF_BHI = 2 * A_T;        // 73728
    constexpr uint32_t OF_BLO = OF_BHI + 2 * B_T;   // 92160
    // total smem = 110592

    extern __shared__ char smem[];
    const uint32_t sbase = smem_u32(smem);

    const int tid = threadIdx.x;
    const int wid = tid >> 5;
    const int n0 = blockIdx.x * BN;
    const int wm = (wid >> 1) * 64;             // 4 m-warps
    const int wn = (wid & 1) * 32;              // 2 n-warps

    // --- A fill (cp.async): 8 chunks, chunk i: row r0+32i, 16B sub q ---
    const int r0 = tid >> 3;            // 0..31
    const int q  = tid & 7;             // 0..7  (16B = 8 fp16 along k)
    const __half* whp = whalf + (size_t)r0 * K + q * 8;
    const uint32_t ad0 = (uint32_t)(r0 * 144 + q * 16);

    // --- B fill: one n, 16 k's per thread ---
    const int n_loc = tid & 63;
    const int koff  = (tid >> 6) * 16;  // 0,16,32,48
    const int n     = n0 + n_loc;
    const int b_    = n / OHW;
    const int rem   = n - b_ * OHW;
    const int ohh   = rem / OW;
    const int oww   = rem - ohh * OW;
    const uint32_t* xb = xp + (size_t)b_ * C * IH * IW + (size_t)ohh * IW + oww;

    auto fillA = [&](int ch) {
        const uint32_t s = sbase + (uint32_t)(ch & 1) * A_T + ad0;
        const int ko = ch * BK;
#pragma unroll
        for (int i = 0; i < 8; i++)
            CP_ASYNC16(s + i * 4608u, whp + ko + (size_t)i * 32 * K);
    };

    auto ldgB = [&](int ch, uint32_t* v) {
        int kg = ch * BK + koff;
        int ci = kg / 9;
        int r9 = kg - ci * 9;
        int kh = r9 / 3;
        int kw = r9 - kh * 3;
#pragma unroll
        for (int j = 0; j < 16; j++) {
            v[j] = __ldg(xb + (ci * IH + kh) * IW + kw);
            kw++; if (kw == 3) { kw = 0; kh++; if (kh == 3) { kh = 0; ci++; } }
        }
    };
    auto stsB = [&](int ch, const uint32_t* v) {
        const int buf = ch & 1;
        uint32_t* dh = (uint32_t*)(smem + OF_BHI + buf * B_T) + n_loc * 36 + (koff >> 1);
        uint32_t* dl = (uint32_t*)(smem + OF_BLO + buf * B_T) + n_loc * 36 + (koff >> 1);
#pragma unroll
        for (int h = 0; h < 2; h++) {
            const uint32_t* s = v + h * 8;
            *reinterpret_cast<uint4*>(dh + h * 4) = make_uint4(
                prmt(s[0], s[1], 0x5410), prmt(s[2], s[3], 0x5410),
                prmt(s[4], s[5], 0x5410), prmt(s[6], s[7], 0x5410));
            *reinterpret_cast<uint4*>(dl + h * 4) = make_uint4(
                prmt(s[0], s[1], 0x7632), prmt(s[2], s[3], 0x7632),
                prmt(s[4], s[5], 0x7632), prmt(s[6], s[7], 0x7632));
        }
    };

    wmma::fragment<wmma::accumulator, 16, 16, 16, float> acc[4][2];
#pragma unroll
    for (int i = 0; i < 4; i++)
#pragma unroll
        for (int j = 0; j < 2; j++) wmma::fill_fragment(acc[i][j], 0.0f);

    // prologue: stage 0
    fillA(0);
    CP_COMMIT();
    {
        uint32_t v[16];
        ldgB(0, v);
        stsB(0, v);
    }

#pragma unroll 1
    for (int ch = 0; ch < NCH; ch++) {
        CP_WAIT0();
        __syncthreads();

        uint32_t v[16];
        const bool more = (ch + 1 < NCH);
        if (more) {
            fillA(ch + 1);
            CP_COMMIT();
            ldgB(ch + 1, v);           // LDGs in flight during MMA below
        }

        const int buf = ch & 1;
        const __half* sa   = (const __half*)(smem + buf * A_T);
        const __half* sb_h = (const __half*)(smem + OF_BHI + buf * B_T);
        const __half* sb_l = (const __half*)(smem + OF_BLO + buf * B_T);

#pragma unroll
        for (int ks = 0; ks < 4; ks++) {
            const int ko = ks * 16;
            wmma::fragment<wmma::matrix_b, 16, 16, 16, __half, wmma::col_major> bh[2], bl[2];
#pragma unroll
            for (int j = 0; j < 2; j++) {
                wmma::load_matrix_sync(bh[j], sb_h + (wn + j * 16) * LDA + ko, LDA);
                wmma::load_matrix_sync(bl[j], sb_l + (wn + j * 16) * LDA + ko, LDA);
            }
#pragma unroll
            for (int i = 0; i < 4; i++) {
                wmma::fragment<wmma::matrix_a, 16, 16, 16, __half, wmma::row_major> a;
                wmma::load_matrix_sync(a, sa + (wm + i * 16) * LDA + ko, LDA);
#pragma unroll
                for (int j = 0; j < 2; j++) {
                    wmma::mma_sync(acc[i][j], a, bh[j], acc[i][j]);
                    wmma::mma_sync(acc[i][j], a, bl[j], acc[i][j]);
                }
            }
        }

        if (more) stsB(ch + 1, v);     // after MMA: LDG latency covered
    }

    // ---- epilogue: acc -> SMEM C tile -> BN -> NCHW scatter ----
    __syncthreads();
    float* ct = (float*)smem;                   // 256 x 68 fp32 = 69632 B
#pragma unroll
    for (int i = 0; i < 4; i++)
#pragma unroll
        for (int j = 0; j < 2; j++)
            wmma::store_matrix_sync(ct + (wm + i * 16) * LDC + wn + j * 16,
                                    acc[i][j], LDC, wmma::mem_row_major);
    __syncthreads();

#pragma unroll 1
    for (int it = 0; it < 64; it++) {
        const int idx = tid + it * 256;
        const int m = idx >> 6;                 // 0..255 (= channel)
        const int nl = idx & 63;
        const float sc = __ldg(&gamma[m]) * rsqrtf(__ldg(&var[m]) + EPS);
        const float bi = __ldg(&beta[m]) - __ldg(&mean[m]) * sc;
        const int nn = n0 + nl;
        const int b2 = nn / OHW;
        const int s  = nn - b2 * OHW;
        out[((size_t)b2 * C + m) * OHW + s] = ct[m * LDC + nl] * sc + bi;
    }
}

// ===========================================================================
// Depthwise cross-correlation: 2 threads per (bc, oh) row.
// Thread half 0: outputs j=0..8 (OFF=0); half 1: j=9..16 (OFF=1, row2 +4).
// ~65 live regs -> 4+ CTAs/SM for latency hiding.
// ===========================================================================
template <int J, int OFF>
__device__ __forceinline__ void xcorr_row(const float* __restrict__ zp,
                                          const float* __restrict__ xp,
                                          int oh, float* __restrict__ op)
{
    float acc[J];
#pragma unroll
    for (int j = 0; j < J; j++) acc[j] = 0.f;

#pragma unroll 1
    for (int p = 0; p < 14; p++) {
        // xr[i] = xf_row[8*OFF + i], i in [0,22)
        const float2* row2 =
            reinterpret_cast<const float2*>(xp + (oh + p) * 30) + OFF * 4;
        float xr[22];
#pragma unroll
        for (int t = 0; t < 11; t++) {
            float2 u = __ldg(row2 + t);
            xr[2 * t] = u.x;
            xr[2 * t + 1] = u.y;
        }
        const float2* zr2 = reinterpret_cast<const float2*>(zp + p * 14);
        float zr[14];
#pragma unroll
        for (int t = 0; t < 7; t++) {
            float2 u = __ldg(zr2 + t);
            zr[2 * t] = u.x;
            zr[2 * t + 1] = u.y;
        }
#pragma unroll
        for (int q = 0; q < 14; q++) {
            float zv = zr[q];
#pragma unroll
            for (int j = 0; j < J; j++)
                acc[j] = fmaf(zv, xr[q + j + OFF], acc[j]);
        }
    }
#pragma unroll
    for (int j = 0; j < J; j++) op[j] = acc[j];
}

__global__ __launch_bounds__(256)
void xcorr_kernel(const float* __restrict__ zf,   // [BC,14,14]
                  const float* __restrict__ xf,   // [BC,30,30]
                  float* __restrict__ out)        // [BC,17,17]
{
    int g = blockIdx.x * blockDim.x + threadIdx.x;
    if (g >= 64 * 256 * 17 * 2) return;
    const int h  = g & 1;
    const int r  = g >> 1;
    const int oh = r % 17;
    const int bc = r / 17;

    const float* zp = zf + bc * 196;
    const float* xp = xf + bc * 900;
    float* op = out + bc * 289 + oh * 17;

    if (h == 0) xcorr_row<9, 0>(zp, xp, oh, op);
    else        xcorr_row<8, 1>(zp, xp, oh, op + 9);
}

// ===========================================================================
extern "C" void kernel_launch(void* const* d_in, const int* in_sizes, int n_in,
                              void* d_out, int out_size)
{
    const float* z       = (const float*)d_in[0];
    const float* x       = (const float*)d_in[1];
    const float* w_z     = (const float*)d_in[2];
    const float* w_x     = (const float*)d_in[3];
    const float* gamma_z = (const float*)d_in[4];
    const float* beta_z  = (const float*)d_in[5];
    const float* mean_z  = (const float*)d_in[6];
    const float* var_z   = (const float*)d_in[7];
    const float* gamma_x = (const float*)d_in[8];
    const float* beta_x  = (const float*)d_in[9];
    const float* mean_x  = (const float*)d_in[10];
    const float* var_x   = (const float*)d_in[11];
    float* out = (float*)d_out;

    float *zf, *xf;
    uint32_t *zp, *xp2;
    __half *wz16, *wx16;
    cudaGetSymbolAddress((void**)&zf, g_zf);
    cudaGetSymbolAddress((void**)&xf, g_xf);
    cudaGetSymbolAddress((void**)&zp, g_zp);
    cudaGetSymbolAddress((void**)&xp2, g_xp);
    cudaGetSymbolAddress((void**)&wz16, g_wz);
    cudaGetSymbolAddress((void**)&wx16, g_wx);

    constexpr int SMEM_BYTES = 110592;

    static cudaStream_t s2 = nullptr;
    static cudaEvent_t e_fork = nullptr, e_join = nullptr;
    if (!s2) {
        cudaFuncSetAttribute(conv3x3_bn_wmma<14, 14, 16, 16>,
                             cudaFuncAttributeMaxDynamicSharedMemorySize, SMEM_BYTES);
        cudaFuncSetAttribute(conv3x3_bn_wmma<30, 30, 32, 32>,
                             cudaFuncAttributeMaxDynamicSharedMemorySize, SMEM_BYTES);
        cudaStreamCreateWithFlags(&s2, cudaStreamNonBlocking);
        cudaEventCreateWithFlags(&e_fork, cudaEventDisableTiming);
        cudaEventCreateWithFlags(&e_join, cudaEventDisableTiming);
    }

    // ---- fork: x-chain on side stream, z-chain on capture (null) stream ----
    cudaEventRecord(e_fork, 0);
    cudaStreamWaitEvent(s2, e_fork, 0);

    // x chain (big): pack x, pack wx, conv_x
    {
        int n4 = 64 * 256 * 32 * 32 / 4;
        pack_in_kernel<<<(n4 + 255) / 256, 256, 0, s2>>>(
            (const float4*)x, (uint4*)xp2, n4);
        n4 = 256 * 2304 / 4;
        pack_w_kernel<<<(n4 + 255) / 256, 256, 0, s2>>>(
            (const float4*)w_x, (uint2*)wx16, n4);
        conv3x3_bn_wmma<30, 30, 32, 32><<<dim3(900, 1), 256, SMEM_BYTES, s2>>>(
            xp2, wx16, gamma_x, beta_x, mean_x, var_x, xf);
    }
    cudaEventRecord(e_join, s2);

    // z chain (small) on the null stream
    {
        int n4 = 64 * 256 * 16 * 16 / 4;
        pack_in_kernel<<<(n4 + 255) / 256, 256>>>(
            (const float4*)z, (uint4*)zp, n4);
        n4 = 256 * 2304 / 4;
        pack_w_kernel<<<(n4 + 255) / 256, 256>>>(
            (const float4*)w_z, (uint2*)wz16, n4);
        conv3x3_bn_wmma<14, 14, 16, 16><<<dim3(196, 1), 256, SMEM_BYTES>>>(
            zp, wz16, gamma_z, beta_z, mean_z, var_z, zf);
    }

    // ---- join, then xcorr ----
    cudaStreamWaitEvent(0, e_join, 0);
    xcorr_kernel<<<2176, 256>>>(zf, xf, out);
}

// round 11
// speedup vs baseline: 1.0090x; 1.0090x over previous
#include <cuda_runtime.h>
#include <cuda_fp16.h>
#include <mma.h>
#include <cstdint>

using namespace nvcuda;

#define EPS 1e-5f

// Scratch (no cudaMalloc allowed).
__device__ __align__(16) float    g_zf[64 * 256 * 14 * 14];     // 12.8 MB
__device__ __align__(16) float    g_xf[64 * 256 * 30 * 30];     // 59 MB
__device__ __align__(16) uint32_t g_zp[64 * 256 * 16 * 16];     // packed z (fp16 hi|lo)
__device__ __align__(16) uint32_t g_xp[64 * 256 * 32 * 32];     // packed x (fp16 hi|lo)
__device__ __align__(16) __half   g_wz[256 * 2304];             // fp16 weights z
__device__ __align__(16) __half   g_wx[256 * 2304];             // fp16 weights x

__device__ __forceinline__ uint32_t prmt(uint32_t a, uint32_t b, uint32_t sel) {
    uint32_t r;
    asm("prmt.b32 %0, %1, %2, %3;" : "=r"(r) : "r"(a), "r"(b), "r"(sel));
    return r;
}

__device__ __forceinline__ uint32_t smem_u32(const void* p) {
    uint32_t a;
    asm("{ .reg .u64 t; cvta.to.shared.u64 t, %1; cvt.u32.u64 %0, t; }"
        : "=r"(a) : "l"(p));
    return a;
}

#define CP_ASYNC16(dst, src) \
    asm volatile("cp.async.cg.shared.global [%0], [%1], 16;" \
        :: "r"(dst), "l"(src) : "memory")
#define CP_COMMIT() asm volatile("cp.async.commit_group;" ::: "memory")
#define CP_WAIT0()  asm volatile("cp.async.wait_group 0;" ::: "memory")

// fp16 2-split pack: u32 = half(v) | half(v - half(v)) << 16
__device__ __forceinline__ uint32_t pack_h2(float v) {
    __half h = __float2half_rn(v);
    __half l = __float2half_rn(v - __half2float(h));
    return (uint32_t)__half_as_ushort(h) |
           ((uint32_t)__half_as_ushort(l) << 16);
}

// ---- pack inputs: fp32 -> u32 (fp16 hi | fp16 lo<<16) ----
__global__ void pack_in_kernel(const float4* __restrict__ src,
                               uint4* __restrict__ dst, int n4)
{
    int i = blockIdx.x * blockDim.x + threadIdx.x;
    if (i >= n4) return;
    float4 v = __ldg(src + i);
    dst[i] = make_uint4(pack_h2(v.x), pack_h2(v.y), pack_h2(v.z), pack_h2(v.w));
}

// ---- pack weights: fp32 -> single fp16 plane ----
__global__ void pack_w_kernel(const float4* __restrict__ src,
                              uint2* __restrict__ dst, int n4)
{
    int i = blockIdx.x * blockDim.x + threadIdx.x;
    if (i >= n4) return;
    float4 v = __ldg(src + i);
    __half2 h01 = __floats2half2_rn(v.x, v.y);
    __half2 h23 = __floats2half2_rn(v.z, v.w);
    dst[i] = make_uint2(*reinterpret_cast<uint32_t*>(&h01),
                        *reinterpret_cast<uint32_t*>(&h23));
}

// ===========================================================================
// Implicit-GEMM 3x3 conv + fused BN, fp16 wmma 2-split.
//   w*x ~= wh*xh + wh*xl  (weights single fp16, inputs split hi/lo)
// BM=256, BN=64, BK=64, 256 threads, warp tile 64x32, 2 CTAs/SM.
// ===========================================================================
template <int OH, int OW, int IH, int IW>
__global__ __launch_bounds__(256, 2)
void conv3x3_bn_wmma(const uint32_t* __restrict__ xp,   // packed input (hi|lo)
                     const __half* __restrict__ whalf,  // fp16 weights [256,2304]
                     const float* __restrict__ gamma,
                     const float* __restrict__ beta,
                     const float* __restrict__ mean,
                     const float* __restrict__ var,
                     float* __restrict__ out)           // [B,256,OH,OW]
{
    constexpr int C = 256, K = C * 9;
    constexpr int BM = 256, BN = 64, BK = 64;
    constexpr int NCH = K / BK;                 // 36
    constexpr int OHW = OH * OW;
    constexpr int LDA = 72;                     // fp16 elems/row (144 B)
    constexpr int LDC = 68;
    constexpr uint32_t A_T = BM * LDA * 2;      // 36864 (single plane)
    constexpr uint32_t B_T = BN * LDA * 2;      // 9216
    constexpr uint32_t OF_BHI = 2 * A_T;        // 73728
    constexpr uint32_t OF_BLO = OF_BHI + 2 * B_T;   // 92160
    // total smem = 110592

    extern __shared__ char smem[];
    const uint32_t sbase = smem_u32(smem);

    const int tid = threadIdx.x;
    const int wid = tid >> 5;
    const int n0 = blockIdx.x * BN;
    const int wm = (wid >> 1) * 64;             // 4 m-warps
    const int wn = (wid & 1) * 32;              // 2 n-warps

    // --- A fill (cp.async): 8 chunks, chunk i: row r0+32i, 16B sub q ---
    const int r0 = tid >> 3;            // 0..31
    const int q  = tid & 7;             // 0..7  (16B = 8 fp16 along k)
    const __half* whp = whalf + (size_t)r0 * K + q * 8;
    const uint32_t ad0 = (uint32_t)(r0 * 144 + q * 16);

    // --- B fill: one n, 16 k's per thread ---
    const int n_loc = tid & 63;
    const int koff  = (tid >> 6) * 16;  // 0,16,32,48
    const int n     = n0 + n_loc;
    const int b_    = n / OHW;
    const int rem   = n - b_ * OHW;
    const int ohh   = rem / OW;
    const int oww   = rem - ohh * OW;
    const uint32_t* xb = xp + (size_t)b_ * C * IH * IW + (size_t)ohh * IW + oww;

    auto fillA = [&](int ch) {
        const uint32_t s = sbase + (uint32_t)(ch & 1) * A_T + ad0;
        const int ko = ch * BK;
#pragma unroll
        for (int i = 0; i < 8; i++)
            CP_ASYNC16(s + i * 4608u, whp + ko + (size_t)i * 32 * K);
    };

    auto ldgB = [&](int ch, uint32_t* v) {
        int kg = ch * BK + koff;
        int ci = kg / 9;
        int r9 = kg - ci * 9;
        int kh = r9 / 3;
        int kw = r9 - kh * 3;
#pragma unroll
        for (int j = 0; j < 16; j++) {
            v[j] = __ldg(xb + (ci * IH + kh) * IW + kw);
            kw++; if (kw == 3) { kw = 0; kh++; if (kh == 3) { kh = 0; ci++; } }
        }
    };
    auto stsB = [&](int ch, const uint32_t* v) {
        const int buf = ch & 1;
        uint32_t* dh = (uint32_t*)(smem + OF_BHI + buf * B_T) + n_loc * 36 + (koff >> 1);
        uint32_t* dl = (uint32_t*)(smem + OF_BLO + buf * B_T) + n_loc * 36 + (koff >> 1);
#pragma unroll
        for (int h = 0; h < 2; h++) {
            const uint32_t* s = v + h * 8;
            *reinterpret_cast<uint4*>(dh + h * 4) = make_uint4(
                prmt(s[0], s[1], 0x5410), prmt(s[2], s[3], 0x5410),
                prmt(s[4], s[5], 0x5410), prmt(s[6], s[7], 0x5410));
            *reinterpret_cast<uint4*>(dl + h * 4) = make_uint4(
                prmt(s[0], s[1], 0x7632), prmt(s[2], s[3], 0x7632),
                prmt(s[4], s[5], 0x7632), prmt(s[6], s[7], 0x7632));
        }
    };

    wmma::fragment<wmma::accumulator, 16, 16, 16, float> acc[4][2];
#pragma unroll
    for (int i = 0; i < 4; i++)
#pragma unroll
        for (int j = 0; j < 2; j++) wmma::fill_fragment(acc[i][j], 0.0f);

    // prologue: stage 0
    fillA(0);
    CP_COMMIT();
    {
        uint32_t v[16];
        ldgB(0, v);
        stsB(0, v);
    }

#pragma unroll 1
    for (int ch = 0; ch < NCH; ch++) {
        CP_WAIT0();
        __syncthreads();

        uint32_t v[16];
        const bool more = (ch + 1 < NCH);
        if (more) {
            fillA(ch + 1);
            CP_COMMIT();
            ldgB(ch + 1, v);           // LDGs in flight during MMA below
        }

        const int buf = ch & 1;
        const __half* sa   = (const __half*)(smem + buf * A_T);
        const __half* sb_h = (const __half*)(smem + OF_BHI + buf * B_T);
        const __half* sb_l = (const __half*)(smem + OF_BLO + buf * B_T);

#pragma unroll
        for (int ks = 0; ks < 4; ks++) {
            const int ko = ks * 16;
            wmma::fragment<wmma::matrix_b, 16, 16, 16, __half, wmma::col_major> bh[2], bl[2];
#pragma unroll
            for (int j = 0; j < 2; j++) {
                wmma::load_matrix_sync(bh[j], sb_h + (wn + j * 16) * LDA + ko, LDA);
                wmma::load_matrix_sync(bl[j], sb_l + (wn + j * 16) * LDA + ko, LDA);
            }
#pragma unroll
            for (int i = 0; i < 4; i++) {
                wmma::fragment<wmma::matrix_a, 16, 16, 16, __half, wmma::row_major> a;
                wmma::load_matrix_sync(a, sa + (wm + i * 16) * LDA + ko, LDA);
#pragma unroll
                for (int j = 0; j < 2; j++) {
                    wmma::mma_sync(acc[i][j], a, bh[j], acc[i][j]);
                    wmma::mma_sync(acc[i][j], a, bl[j], acc[i][j]);
                }
            }
        }

        if (more) stsB(ch + 1, v);     // after MMA: LDG latency covered
    }

    // ---- epilogue: acc -> SMEM C tile -> BN -> NCHW scatter ----
    __syncthreads();
    float* ct = (float*)smem;                   // 256 x 68 fp32 = 69632 B
#pragma unroll
    for (int i = 0; i < 4; i++)
#pragma unroll
        for (int j = 0; j < 2; j++)
            wmma::store_matrix_sync(ct + (wm + i * 16) * LDC + wn + j * 16,
                                    acc[i][j], LDC, wmma::mem_row_major);
    __syncthreads();

#pragma unroll 1
    for (int it = 0; it < 64; it++) {
        const int idx = tid + it * 256;
        const int m = idx >> 6;                 // 0..255 (= channel)
        const int nl = idx & 63;
        const float sc = __ldg(&gamma[m]) * rsqrtf(__ldg(&var[m]) + EPS);
        const float bi = __ldg(&beta[m]) - __ldg(&mean[m]) * sc;
        const int nn = n0 + nl;
        const int b2 = nn / OHW;
        const int s  = nn - b2 * OHW;
        out[((size_t)b2 * C + m) * OHW + s] = ct[m * LDC + nl] * sc + bi;
    }
}

// ===========================================================================
// Depthwise cross-correlation: 2 threads per (bc, oh) row, GRID-UNIFORM halves
// (g < R -> outputs j=0..8; g >= R -> j=9..16) so warps never diverge.
// ~60 live regs -> 3-4 CTAs/SM of latency hiding.
// ===========================================================================
template <int J, int OFF>
__device__ __forceinline__ void xcorr_row(const float* __restrict__ zp,
                                          const float* __restrict__ xp,
                                          int oh, float* __restrict__ op)
{
    float acc[J];
#pragma unroll
    for (int j = 0; j < J; j++) acc[j] = 0.f;

#pragma unroll 1
    for (int p = 0; p < 14; p++) {
        // xr[i] = xf_row[8*OFF + i], i in [0,22)
        const float2* row2 =
            reinterpret_cast<const float2*>(xp + (oh + p) * 30) + OFF * 4;
        float xr[22];
#pragma unroll
        for (int t = 0; t < 11; t++) {
            float2 u = __ldg(row2 + t);
            xr[2 * t] = u.x;
            xr[2 * t + 1] = u.y;
        }
        const float2* zr2 = reinterpret_cast<const float2*>(zp + p * 14);
        float zr[14];
#pragma unroll
        for (int t = 0; t < 7; t++) {
            float2 u = __ldg(zr2 + t);
            zr[2 * t] = u.x;
            zr[2 * t + 1] = u.y;
        }
#pragma unroll
        for (int q = 0; q < 14; q++) {
            float zv = zr[q];
#pragma unroll
            for (int j = 0; j < J; j++)
                acc[j] = fmaf(zv, xr[q + j + OFF], acc[j]);
        }
    }
#pragma unroll
    for (int j = 0; j < J; j++) op[j] = acc[j];
}

__global__ __launch_bounds__(256)
void xcorr_kernel(const float* __restrict__ zf,   // [BC,14,14]
                  const float* __restrict__ xf,   // [BC,30,30]
                  float* __restrict__ out)        // [BC,17,17]
{
    constexpr int R = 64 * 256 * 17;            // rows total (= 1088 * 256)
    int g = blockIdx.x * blockDim.x + threadIdx.x;
    const int h = (g >= R) ? 1 : 0;             // grid-uniform: whole block same h
    const int r = g - h * R;
    const int oh = r % 17;
    const int bc = r / 17;

    const float* zp = zf + bc * 196;
    const float* xp = xf + bc * 900;
    float* op = out + bc * 289 + oh * 17;

    if (h == 0) xcorr_row<9, 0>(zp, xp, oh, op);
    else        xcorr_row<8, 1>(zp, xp, oh, op + 9);
}

// ===========================================================================
extern "C" void kernel_launch(void* const* d_in, const int* in_sizes, int n_in,
                              void* d_out, int out_size)
{
    const float* z       = (const float*)d_in[0];
    const float* x       = (const float*)d_in[1];
    const float* w_z     = (const float*)d_in[2];
    const float* w_x     = (const float*)d_in[3];
    const float* gamma_z = (const float*)d_in[4];
    const float* beta_z  = (const float*)d_in[5];
    const float* mean_z  = (const float*)d_in[6];
    const float* var_z   = (const float*)d_in[7];
    const float* gamma_x = (const float*)d_in[8];
    const float* beta_x  = (const float*)d_in[9];
    const float* mean_x  = (const float*)d_in[10];
    const float* var_x   = (const float*)d_in[11];
    float* out = (float*)d_out;

    float *zf, *xf;
    uint32_t *zp, *xp2;
    __half *wz16, *wx16;
    cudaGetSymbolAddress((void**)&zf, g_zf);
    cudaGetSymbolAddress((void**)&xf, g_xf);
    cudaGetSymbolAddress((void**)&zp, g_zp);
    cudaGetSymbolAddress((void**)&xp2, g_xp);
    cudaGetSymbolAddress((void**)&wz16, g_wz);
    cudaGetSymbolAddress((void**)&wx16, g_wx);

    constexpr int SMEM_BYTES = 110592;

    static cudaStream_t s2 = nullptr;
    static cudaEvent_t e_fork = nullptr, e_join = nullptr;
    if (!s2) {
        cudaFuncSetAttribute(conv3x3_bn_wmma<14, 14, 16, 16>,
                             cudaFuncAttributeMaxDynamicSharedMemorySize, SMEM_BYTES);
        cudaFuncSetAttribute(conv3x3_bn_wmma<30, 30, 32, 32>,
                             cudaFuncAttributeMaxDynamicSharedMemorySize, SMEM_BYTES);
        cudaStreamCreateWithFlags(&s2, cudaStreamNonBlocking);
        cudaEventCreateWithFlags(&e_fork, cudaEventDisableTiming);
        cudaEventCreateWithFlags(&e_join, cudaEventDisableTiming);
    }

    // ---- fork: x-chain on side stream, z-chain on capture (null) stream ----
    cudaEventRecord(e_fork, 0);
    cudaStreamWaitEvent(s2, e_fork, 0);

    // x chain (big): pack x, pack wx, conv_x
    {
        int n4 = 64 * 256 * 32 * 32 / 4;
        pack_in_kernel<<<(n4 + 255) / 256, 256, 0, s2>>>(
            (const float4*)x, (uint4*)xp2, n4);
        n4 = 256 * 2304 / 4;
        pack_w_kernel<<<(n4 + 255) / 256, 256, 0, s2>>>(
            (const float4*)w_x, (uint2*)wx16, n4);
        conv3x3_bn_wmma<30, 30, 32, 32><<<dim3(900, 1), 256, SMEM_BYTES, s2>>>(
            xp2, wx16, gamma_x, beta_x, mean_x, var_x, xf);
    }
    cudaEventRecord(e_join, s2);

    // z chain (small) on the null stream
    {
        int n4 = 64 * 256 * 16 * 16 / 4;
        pack_in_kernel<<<(n4 + 255) / 256, 256>>>(
            (const float4*)z, (uint4*)zp, n4);
        n4 = 256 * 2304 / 4;
        pack_w_kernel<<<(n4 + 255) / 256, 256>>>(
            (const float4*)w_z, (uint2*)wz16, n4);
        conv3x3_bn_wmma<14, 14, 16, 16><<<dim3(196, 1), 256, SMEM_BYTES>>>(
            zp, wz16, gamma_z, beta_z, mean_z, var_z, zf);
    }

    // ---- join, then xcorr (2R threads = 2176 blocks) ----
    cudaStreamWaitEvent(0, e_join, 0);
    xcorr_kernel<<<2176, 256>>>(zf, xf, out);
}

// round 12
// speedup vs baseline: 1.0525x; 1.0432x over previous
#include <cuda_runtime.h>
#include <cuda_fp16.h>
#include <mma.h>
#include <cstdint>

using namespace nvcuda;

#define EPS 1e-5f

// Scratch (no cudaMalloc allowed).
__device__ __align__(16) float    g_zf[64 * 256 * 14 * 14];     // 12.8 MB
__device__ __align__(16) float    g_xf[64 * 256 * 30 * 30];     // 59 MB
__device__ __align__(16) uint32_t g_zp[64 * 256 * 16 * 16];     // packed z (fp16 hi|lo)
__device__ __align__(16) uint32_t g_xp[64 * 256 * 32 * 32];     // packed x (fp16 hi|lo)
__device__ __align__(16) __half   g_wz[256 * 2304];             // fp16 weights z
__device__ __align__(16) __half   g_wx[256 * 2304];             // fp16 weights x

__device__ __forceinline__ uint32_t prmt(uint32_t a, uint32_t b, uint32_t sel) {
    uint32_t r;
    asm("prmt.b32 %0, %1, %2, %3;" : "=r"(r) : "r"(a), "r"(b), "r"(sel));
    return r;
}

__device__ __forceinline__ uint32_t smem_u32(const void* p) {
    uint32_t a;
    asm("{ .reg .u64 t; cvta.to.shared.u64 t, %1; cvt.u32.u64 %0, t; }"
        : "=r"(a) : "l"(p));
    return a;
}

#define CP_ASYNC16(dst, src) \
    asm volatile("cp.async.cg.shared.global [%0], [%1], 16;" \
        :: "r"(dst), "l"(src) : "memory")
#define CP_COMMIT() asm volatile("cp.async.commit_group;" ::: "memory")
#define CP_WAIT0()  asm volatile("cp.async.wait_group 0;" ::: "memory")

// fp16 2-split pack: u32 = half(v) | half(v - half(v)) << 16
__device__ __forceinline__ uint32_t pack_h2(float v) {
    __half h = __float2half_rn(v);
    __half l = __float2half_rn(v - __half2float(h));
    return (uint32_t)__half_as_ushort(h) |
           ((uint32_t)__half_as_ushort(l) << 16);
}

// ---- pack inputs: fp32 -> u32 (fp16 hi | fp16 lo<<16) ----
__global__ void pack_in_kernel(const float4* __restrict__ src,
                               uint4* __restrict__ dst, int n4)
{
    int i = blockIdx.x * blockDim.x + threadIdx.x;
    if (i >= n4) return;
    float4 v = __ldg(src + i);
    dst[i] = make_uint4(pack_h2(v.x), pack_h2(v.y), pack_h2(v.z), pack_h2(v.w));
}

// ---- pack weights: fp32 -> single fp16 plane ----
__global__ void pack_w_kernel(const float4* __restrict__ src,
                              uint2* __restrict__ dst, int n4)
{
    int i = blockIdx.x * blockDim.x + threadIdx.x;
    if (i >= n4) return;
    float4 v = __ldg(src + i);
    __half2 h01 = __floats2half2_rn(v.x, v.y);
    __half2 h23 = __floats2half2_rn(v.z, v.w);
    dst[i] = make_uint2(*reinterpret_cast<uint32_t*>(&h01),
                        *reinterpret_cast<uint32_t*>(&h23));
}

// ===========================================================================
// Implicit-GEMM 3x3 conv + fused BN, fp16 wmma 2-split.
//   w*x ~= wh*xh + wh*xl  (weights single fp16, inputs split hi/lo)
// BM=256, BN=64, BK=64, 256 threads, warp tile 64x32, 2 CTAs/SM.
// ===========================================================================
template <int OH, int OW, int IH, int IW>
__global__ __launch_bounds__(256, 2)
void conv3x3_bn_wmma(const uint32_t* __restrict__ xp,   // packed input (hi|lo)
                     const __half* __restrict__ whalf,  // fp16 weights [256,2304]
                     const float* __restrict__ gamma,
                     const float* __restrict__ beta,
                     const float* __restrict__ mean,
                     const float* __restrict__ var,
                     float* __restrict__ out)           // [B,256,OH,OW]
{
    constexpr int C = 256, K = C * 9;
    constexpr int BM = 256, BN = 64, BK = 64;
    constexpr int NCH = K / BK;                 // 36
    constexpr int OHW = OH * OW;
    constexpr int LDA = 72;                     // fp16 elems/row (144 B)
    constexpr int LDC = 68;
    constexpr uint32_t A_T = BM * LDA * 2;      // 36864 (single plane)
    constexpr uint32_t B_T = BN * LDA * 2;      // 9216
    constexpr uint32_t OF_BHI = 2 * A_T;        // 73728
    constexpr uint32_t OF_BLO = OF_BHI + 2 * B_T;   // 92160
    // total smem = 110592

    extern __shared__ char smem[];
    const uint32_t sbase = smem_u32(smem);

    const int tid = threadIdx.x;
    const int wid = tid >> 5;
    const int n0 = blockIdx.x * BN;
    const int wm = (wid >> 1) * 64;             // 4 m-warps
    const int wn = (wid & 1) * 32;              // 2 n-warps

    // --- A fill (cp.async): 8 chunks, chunk i: row r0+32i, 16B sub q ---
    const int r0 = tid >> 3;            // 0..31
    const int q  = tid & 7;             // 0..7  (16B = 8 fp16 along k)
    const __half* whp = whalf + (size_t)r0 * K + q * 8;
    const uint32_t ad0 = (uint32_t)(r0 * 144 + q * 16);

    // --- B fill: one n, 16 k's per thread ---
    const int n_loc = tid & 63;
    const int koff  = (tid >> 6) * 16;  // 0,16,32,48
    const int n     = n0 + n_loc;
    const int b_    = n / OHW;
    const int rem   = n - b_ * OHW;
    const int ohh   = rem / OW;
    const int oww   = rem - ohh * OW;
    const uint32_t* xb = xp + (size_t)b_ * C * IH * IW + (size_t)ohh * IW + oww;

    auto fillA = [&](int ch) {
        const uint32_t s = sbase + (uint32_t)(ch & 1) * A_T + ad0;
        const int ko = ch * BK;
#pragma unroll
        for (int i = 0; i < 8; i++)
            CP_ASYNC16(s + i * 4608u, whp + ko + (size_t)i * 32 * K);
    };

    auto ldgB = [&](int ch, uint32_t* v) {
        int kg = ch * BK + koff;
        int ci = kg / 9;
        int r9 = kg - ci * 9;
        int kh = r9 / 3;
        int kw = r9 - kh * 3;
#pragma unroll
        for (int j = 0; j < 16; j++) {
            v[j] = __ldg(xb + (ci * IH + kh) * IW + kw);
            kw++; if (kw == 3) { kw = 0; kh++; if (kh == 3) { kh = 0; ci++; } }
        }
    };
    auto stsB = [&](int ch, const uint32_t* v) {
        const int buf = ch & 1;
        uint32_t* dh = (uint32_t*)(smem + OF_BHI + buf * B_T) + n_loc * 36 + (koff >> 1);
        uint32_t* dl = (uint32_t*)(smem + OF_BLO + buf * B_T) + n_loc * 36 + (koff >> 1);
#pragma unroll
        for (int h = 0; h < 2; h++) {
            const uint32_t* s = v + h * 8;
            *reinterpret_cast<uint4*>(dh + h * 4) = make_uint4(
                prmt(s[0], s[1], 0x5410), prmt(s[2], s[3], 0x5410),
                prmt(s[4], s[5], 0x5410), prmt(s[6], s[7], 0x5410));
            *reinterpret_cast<uint4*>(dl + h * 4) = make_uint4(
                prmt(s[0], s[1], 0x7632), prmt(s[2], s[3], 0x7632),
                prmt(s[4], s[5], 0x7632), prmt(s[6], s[7], 0x7632));
        }
    };

    wmma::fragment<wmma::accumulator, 16, 16, 16, float> acc[4][2];
#pragma unroll
    for (int i = 0; i < 4; i++)
#pragma unroll
        for (int j = 0; j < 2; j++) wmma::fill_fragment(acc[i][j], 0.0f);

    // prologue: stage 0
    fillA(0);
    CP_COMMIT();
    {
        uint32_t v[16];
        ldgB(0, v);
        stsB(0, v);
    }

#pragma unroll 1
    for (int ch = 0; ch < NCH; ch++) {
        CP_WAIT0();
        __syncthreads();

        uint32_t v[16];
        const bool more = (ch + 1 < NCH);
        if (more) {
            fillA(ch + 1);
            CP_COMMIT();
            ldgB(ch + 1, v);           // LDGs in flight during MMA below
        }

        const int buf = ch & 1;
        const __half* sa   = (const __half*)(smem + buf * A_T);
        const __half* sb_h = (const __half*)(smem + OF_BHI + buf * B_T);
        const __half* sb_l = (const __half*)(smem + OF_BLO + buf * B_T);

#pragma unroll
        for (int ks = 0; ks < 4; ks++) {
            const int ko = ks * 16;
            wmma::fragment<wmma::matrix_b, 16, 16, 16, __half, wmma::col_major> bh[2], bl[2];
#pragma unroll
            for (int j = 0; j < 2; j++) {
                wmma::load_matrix_sync(bh[j], sb_h + (wn + j * 16) * LDA + ko, LDA);
                wmma::load_matrix_sync(bl[j], sb_l + (wn + j * 16) * LDA + ko, LDA);
            }
#pragma unroll
            for (int i = 0; i < 4; i++) {
                wmma::fragment<wmma::matrix_a, 16, 16, 16, __half, wmma::row_major> a;
                wmma::load_matrix_sync(a, sa + (wm + i * 16) * LDA + ko, LDA);
#pragma unroll
                for (int j = 0; j < 2; j++) {
                    wmma::mma_sync(acc[i][j], a, bh[j], acc[i][j]);
                    wmma::mma_sync(acc[i][j], a, bl[j], acc[i][j]);
                }
            }
        }

        if (more) stsB(ch + 1, v);     // after MMA: LDG latency covered
    }

    // ---- epilogue: acc -> SMEM C tile -> BN -> NCHW scatter ----
    __syncthreads();
    float* ct = (float*)smem;                   // 256 x 68 fp32 = 69632 B
#pragma unroll
    for (int i = 0; i < 4; i++)
#pragma unroll
        for (int j = 0; j < 2; j++)
            wmma::store_matrix_sync(ct + (wm + i * 16) * LDC + wn + j * 16,
                                    acc[i][j], LDC, wmma::mem_row_major);
    __syncthreads();

#pragma unroll 1
    for (int it = 0; it < 64; it++) {
        const int idx = tid + it * 256;
        const int m = idx >> 6;                 // 0..255 (= channel)
        const int nl = idx & 63;
        const float sc = __ldg(&gamma[m]) * rsqrtf(__ldg(&var[m]) + EPS);
        const float bi = __ldg(&beta[m]) - __ldg(&mean[m]) * sc;
        const int nn = n0 + nl;
        const int b2 = nn / OHW;
        const int s  = nn - b2 * OHW;
        out[((size_t)b2 * C + m) * OHW + s] = ct[m * LDC + nl] * sc + bi;
    }
}

// ===========================================================================
// Depthwise cross-correlation (monolithic, float2-vectorized — the proven
// R9 configuration: one thread per (bc, oh) row, 17 accumulators).
// ===========================================================================
__global__ __launch_bounds__(256)
void xcorr_kernel(const float* __restrict__ zf,   // [BC,14,14]
                  const float* __restrict__ xf,   // [BC,30,30]
                  float* __restrict__ out)        // [BC,17,17]
{
    int g = blockIdx.x * blockDim.x + threadIdx.x;
    if (g >= 64 * 256 * 17) return;
    int oh = g % 17;
    int bc = g / 17;

    const float* zp = zf + bc * 196;
    const float* xp = xf + bc * 900;

    float acc[17];
#pragma unroll
    for (int j = 0; j < 17; j++) acc[j] = 0.f;

#pragma unroll 1
    for (int p = 0; p < 14; p++) {
        const float2* row2 = reinterpret_cast<const float2*>(xp + (oh + p) * 30);
        float xr[30];
#pragma unroll
        for (int t = 0; t < 15; t++) {
            float2 u = __ldg(row2 + t);
            xr[2 * t] = u.x;
            xr[2 * t + 1] = u.y;
        }
        const float2* zr2 = reinterpret_cast<const float2*>(zp + p * 14);
        float zr[14];
#pragma unroll
        for (int t = 0; t < 7; t++) {
            float2 u = __ldg(zr2 + t);
            zr[2 * t] = u.x;
            zr[2 * t + 1] = u.y;
        }
#pragma unroll
        for (int q = 0; q < 14; q++) {
            float zv = zr[q];
#pragma unroll
            for (int j = 0; j < 17; j++)
                acc[j] = fmaf(zv, xr[q + j], acc[j]);
        }
    }

    float* op = out + bc * 289 + oh * 17;
#pragma unroll
    for (int j = 0; j < 17; j++) op[j] = acc[j];
}

// ===========================================================================
extern "C" void kernel_launch(void* const* d_in, const int* in_sizes, int n_in,
                              void* d_out, int out_size)
{
    const float* z       = (const float*)d_in[0];
    const float* x       = (const float*)d_in[1];
    const float* w_z     = (const float*)d_in[2];
    const float* w_x     = (const float*)d_in[3];
    const float* gamma_z = (const float*)d_in[4];
    const float* beta_z  = (const float*)d_in[5];
    const float* mean_z  = (const float*)d_in[6];
    const float* var_z   = (const float*)d_in[7];
    const float* gamma_x = (const float*)d_in[8];
    const float* beta_x  = (const float*)d_in[9];
    const float* mean_x  = (const float*)d_in[10];
    const float* var_x   = (const float*)d_in[11];
    float* out = (float*)d_out;

    float *zf, *xf;
    uint32_t *zp, *xp2;
    __half *wz16, *wx16;
    cudaGetSymbolAddress((void**)&zf, g_zf);
    cudaGetSymbolAddress((void**)&xf, g_xf);
    cudaGetSymbolAddress((void**)&zp, g_zp);
    cudaGetSymbolAddress((void**)&xp2, g_xp);
    cudaGetSymbolAddress((void**)&wz16, g_wz);
    cudaGetSymbolAddress((void**)&wx16, g_wx);

    constexpr int SMEM_BYTES = 110592;

    static cudaStream_t s2 = nullptr;
    static cudaEvent_t e_fork = nullptr, e_join = nullptr;
    if (!s2) {
        cudaFuncSetAttribute(conv3x3_bn_wmma<14, 14, 16, 16>,
                             cudaFuncAttributeMaxDynamicSharedMemorySize, SMEM_BYTES);
        cudaFuncSetAttribute(conv3x3_bn_wmma<30, 30, 32, 32>,
                             cudaFuncAttributeMaxDynamicSharedMemorySize, SMEM_BYTES);
        cudaStreamCreateWithFlags(&s2, cudaStreamNonBlocking);
        cudaEventCreateWithFlags(&e_fork, cudaEventDisableTiming);
        cudaEventCreateWithFlags(&e_join, cudaEventDisableTiming);
    }

    // ---- fork: x-chain on side stream, z-chain on capture (null) stream ----
    cudaEventRecord(e_fork, 0);
    cudaStreamWaitEvent(s2, e_fork, 0);

    // x chain (big): pack x, pack wx, conv_x
    {
        int n4 = 64 * 256 * 32 * 32 / 4;
        pack_in_kernel<<<(n4 + 255) / 256, 256, 0, s2>>>(
            (const float4*)x, (uint4*)xp2, n4);
        n4 = 256 * 2304 / 4;
        pack_w_kernel<<<(n4 + 255) / 256, 256, 0, s2>>>(
            (const float4*)w_x, (uint2*)wx16, n4);
        conv3x3_bn_wmma<30, 30, 32, 32><<<dim3(900, 1), 256, SMEM_BYTES, s2>>>(
            xp2, wx16, gamma_x, beta_x, mean_x, var_x, xf);
    }
    cudaEventRecord(e_join, s2);

    // z chain (small) on the null stream
    {
        int n4 = 64 * 256 * 16 * 16 / 4;
        pack_in_kernel<<<(n4 + 255) / 256, 256>>>(
            (const float4*)z, (uint4*)zp, n4);
        n4 = 256 * 2304 / 4;
        pack_w_kernel<<<(n4 + 255) / 256, 256>>>(
            (const float4*)w_z, (uint2*)wz16, n4);
        conv3x3_bn_wmma<14, 14, 16, 16><<<dim3(196, 1), 256, SMEM_BYTES>>>(
            zp, wz16, gamma_z, beta_z, mean_z, var_z, zf);
    }

    // ---- join, then xcorr ----
    cudaStreamWaitEvent(0, e_join, 0);
    xcorr_kernel<<<1088, 256>>>(zf, xf, out);
}

// round 13
// speedup vs baseline: 1.4375x; 1.3657x over previous
#include <cuda_runtime.h>
#include <cuda_fp16.h>
#include <mma.h>
#include <cstdint>

using namespace nvcuda;

#define EPS 1e-5f

// Scratch (no cudaMalloc allowed).
__device__ __align__(16) float    g_zf[64 * 256 * 14 * 14];     // 12.8 MB
__device__ __align__(16) float    g_xf[64 * 256 * 30 * 30];     // 59 MB
__device__ __align__(16) __half   g_zp[64 * 256 * 16 * 16];     // fp16 z
__device__ __align__(16) __half   g_xp[64 * 256 * 32 * 32];     // fp16 x
__device__ __align__(16) __half   g_wz[256 * 2304];             // fp16 weights z
__device__ __align__(16) __half   g_wx[256 * 2304];             // fp16 weights x

__device__ __forceinline__ uint32_t smem_u32(const void* p) {
    uint32_t a;
    asm("{ .reg .u64 t; cvta.to.shared.u64 t, %1; cvt.u32.u64 %0, t; }"
        : "=r"(a) : "l"(p));
    return a;
}

#define CP_ASYNC16(dst, src) \
    asm volatile("cp.async.cg.shared.global [%0], [%1], 16;" \
        :: "r"(dst), "l"(src) : "memory")
#define CP_COMMIT() asm volatile("cp.async.commit_group;" ::: "memory")
#define CP_WAIT0()  asm volatile("cp.async.wait_group 0;" ::: "memory")

// ---- pack fp32 -> fp16 plane (used for inputs AND weights) ----
__global__ void pack_h_kernel(const float4* __restrict__ src,
                              uint2* __restrict__ dst, int n4)
{
    int i = blockIdx.x * blockDim.x + threadIdx.x;
    if (i >= n4) return;
    float4 v = __ldg(src + i);
    __half2 h01 = __floats2half2_rn(v.x, v.y);
    __half2 h23 = __floats2half2_rn(v.z, v.w);
    dst[i] = make_uint2(*reinterpret_cast<uint32_t*>(&h01),
                        *reinterpret_cast<uint32_t*>(&h23));
}

// ===========================================================================
// Implicit-GEMM 3x3 conv + fused BN, single-pass fp16 wmma.
// BM=256, BN=64, BK=64, 256 threads, warp tile 64x32, 2 CTAs/SM.
// A (weights) cp.async double-buffered; B (im2col fp16 gather) reg-staged.
// ===========================================================================
template <int OH, int OW, int IH, int IW>
__global__ __launch_bounds__(256, 2)
void conv3x3_bn_wmma(const __half* __restrict__ xph,   // fp16 input [B,256,IH,IW]
                     const __half* __restrict__ whalf, // fp16 weights [256,2304]
                     const float* __restrict__ gamma,
                     const float* __restrict__ beta,
                     const float* __restrict__ mean,
                     const float* __restrict__ var,
                     float* __restrict__ out)          // [B,256,OH,OW]
{
    constexpr int C = 256, K = C * 9;
    constexpr int BM = 256, BN = 64, BK = 64;
    constexpr int NCH = K / BK;                 // 36
    constexpr int OHW = OH * OW;
    constexpr int LDA = 72;                     // fp16 elems/row (144 B)
    constexpr int LDC = 68;
    constexpr uint32_t A_T = BM * LDA * 2;      // 36864
    constexpr uint32_t B_T = BN * LDA * 2;      // 9216
    constexpr uint32_t OF_B = 2 * A_T;          // 73728
    // total smem = 92160

    extern __shared__ char smem[];
    const uint32_t sbase = smem_u32(smem);

    const int tid = threadIdx.x;
    const int wid = tid >> 5;
    const int n0 = blockIdx.x * BN;
    const int wm = (wid >> 1) * 64;             // 4 m-warps
    const int wn = (wid & 1) * 32;              // 2 n-warps

    // --- A fill (cp.async): 8 chunks, chunk i: row r0+32i, 16B sub q ---
    const int r0 = tid >> 3;            // 0..31
    const int q  = tid & 7;             // 0..7
    const __half* whp = whalf + (size_t)r0 * K + q * 8;
    const uint32_t ad0 = (uint32_t)(r0 * 144 + q * 16);

    // --- B fill: one n, 16 k's per thread ---
    const int n_loc = tid & 63;
    const int koff  = (tid >> 6) * 16;  // 0,16,32,48
    const int n     = n0 + n_loc;
    const int b_    = n / OHW;
    const int rem   = n - b_ * OHW;
    const int ohh   = rem / OW;
    const int oww   = rem - ohh * OW;
    const __half* xb = xph + (size_t)b_ * C * IH * IW + (size_t)ohh * IW + oww;

    auto fillA = [&](int ch) {
        const uint32_t s = sbase + (uint32_t)(ch & 1) * A_T + ad0;
        const int ko = ch * BK;
#pragma unroll
        for (int i = 0; i < 8; i++)
            CP_ASYNC16(s + i * 4608u, whp + ko + (size_t)i * 32 * K);
    };

    auto ldgB = [&](int ch, uint32_t* v) {
        int kg = ch * BK + koff;
        int ci = kg / 9;
        int r9 = kg - ci * 9;
        int kh = r9 / 3;
        int kw = r9 - kh * 3;
#pragma unroll
        for (int j = 0; j < 16; j++) {
            v[j] = (uint32_t)__half_as_ushort(__ldg(xb + (ci * IH + kh) * IW + kw));
            kw++; if (kw == 3) { kw = 0; kh++; if (kh == 3) { kh = 0; ci++; } }
        }
    };
    auto stsB = [&](int ch, const uint32_t* v) {
        const int buf = ch & 1;
        uint32_t* db = (uint32_t*)(smem + OF_B + buf * B_T) + n_loc * 36 + (koff >> 1);
#pragma unroll
        for (int h = 0; h < 2; h++) {
            const uint32_t* s = v + h * 8;
            *reinterpret_cast<uint4*>(db + h * 4) = make_uint4(
                s[0] | (s[1] << 16), s[2] | (s[3] << 16),
                s[4] | (s[5] << 16), s[6] | (s[7] << 16));
        }
    };

    wmma::fragment<wmma::accumulator, 16, 16, 16, float> acc[4][2];
#pragma unroll
    for (int i = 0; i < 4; i++)
#pragma unroll
        for (int j = 0; j < 2; j++) wmma::fill_fragment(acc[i][j], 0.0f);

    // prologue: stage 0
    fillA(0);
    CP_COMMIT();
    {
        uint32_t v[16];
        ldgB(0, v);
        stsB(0, v);
    }

#pragma unroll 1
    for (int ch = 0; ch < NCH; ch++) {
        CP_WAIT0();
        __syncthreads();

        uint32_t v[16];
        const bool more = (ch + 1 < NCH);
        if (more) {
            fillA(ch + 1);
            CP_COMMIT();
            ldgB(ch + 1, v);           // LDGs in flight during MMA below
        }

        const int buf = ch & 1;
        const __half* sa = (const __half*)(smem + buf * A_T);
        const __half* sb = (const __half*)(smem + OF_B + buf * B_T);

#pragma unroll
        for (int ks = 0; ks < 4; ks++) {
            const int ko = ks * 16;
            wmma::fragment<wmma::matrix_b, 16, 16, 16, __half, wmma::col_major> b[2];
#pragma unroll
            for (int j = 0; j < 2; j++)
                wmma::load_matrix_sync(b[j], sb + (wn + j * 16) * LDA + ko, LDA);
#pragma unroll
            for (int i = 0; i < 4; i++) {
                wmma::fragment<wmma::matrix_a, 16, 16, 16, __half, wmma::row_major> a;
                wmma::load_matrix_sync(a, sa + (wm + i * 16) * LDA + ko, LDA);
#pragma unroll
                for (int j = 0; j < 2; j++)
                    wmma::mma_sync(acc[i][j], a, b[j], acc[i][j]);
            }
        }

        if (more) stsB(ch + 1, v);     // after MMA: LDG latency covered
    }

    // ---- epilogue: acc -> SMEM C tile -> BN -> NCHW scatter ----
    __syncthreads();
    float* ct = (float*)smem;                   // 256 x 68 fp32 = 69632 B
#pragma unroll
    for (int i = 0; i < 4; i++)
#pragma unroll
        for (int j = 0; j < 2; j++)
            wmma::store_matrix_sync(ct + (wm + i * 16) * LDC + wn + j * 16,
                                    acc[i][j], LDC, wmma::mem_row_major);
    __syncthreads();

#pragma unroll 1
    for (int it = 0; it < 64; it++) {
        const int idx = tid + it * 256;
        const int m = idx >> 6;                 // 0..255 (= channel)
        const int nl = idx & 63;
        const float sc = __ldg(&gamma[m]) * rsqrtf(__ldg(&var[m]) + EPS);
        const float bi = __ldg(&beta[m]) - __ldg(&mean[m]) * sc;
        const int nn = n0 + nl;
        const int b2 = nn / OHW;
        const int s  = nn - b2 * OHW;
        out[((size_t)b2 * C + m) * OHW + s] = ct[m * LDC + nl] * sc + bi;
    }
}

// ===========================================================================
// Depthwise cross-correlation (monolithic, float2-vectorized; proven config).
// ===========================================================================
__global__ __launch_bounds__(256)
void xcorr_kernel(const float* __restrict__ zf,   // [BC,14,14]
                  const float* __restrict__ xf,   // [BC,30,30]
                  float* __restrict__ out)        // [BC,17,17]
{
    int g = blockIdx.x * blockDim.x + threadIdx.x;
    if (g >= 64 * 256 * 17) return;
    int oh = g % 17;
    int bc = g / 17;

    const float* zp = zf + bc * 196;
    const float* xp = xf + bc * 900;

    float acc[17];
#pragma unroll
    for (int j = 0; j < 17; j++) acc[j] = 0.f;

#pragma unroll 1
    for (int p = 0; p < 14; p++) {
        const float2* row2 = reinterpret_cast<const float2*>(xp + (oh + p) * 30);
        float xr[30];
#pragma unroll
        for (int t = 0; t < 15; t++) {
            float2 u = __ldg(row2 + t);
            xr[2 * t] = u.x;
            xr[2 * t + 1] = u.y;
        }
        const float2* zr2 = reinterpret_cast<const float2*>(zp + p * 14);
        float zr[14];
#pragma unroll
        for (int t = 0; t < 7; t++) {
            float2 u = __ldg(zr2 + t);
            zr[2 * t] = u.x;
            zr[2 * t + 1] = u.y;
        }
#pragma unroll
        for (int q = 0; q < 14; q++) {
            float zv = zr[q];
#pragma unroll
            for (int j = 0; j < 17; j++)
                acc[j] = fmaf(zv, xr[q + j], acc[j]);
        }
    }

    float* op = out + bc * 289 + oh * 17;
#pragma unroll
    for (int j = 0; j < 17; j++) op[j] = acc[j];
}

// ===========================================================================
extern "C" void kernel_launch(void* const* d_in, const int* in_sizes, int n_in,
                              void* d_out, int out_size)
{
    const float* z       = (const float*)d_in[0];
    const float* x       = (const float*)d_in[1];
    const float* w_z     = (const float*)d_in[2];
    const float* w_x     = (const float*)d_in[3];
    const float* gamma_z = (const float*)d_in[4];
    const float* beta_z  = (const float*)d_in[5];
    const float* mean_z  = (const float*)d_in[6];
    const float* var_z   = (const float*)d_in[7];
    const float* gamma_x = (const float*)d_in[8];
    const float* beta_x  = (const float*)d_in[9];
    const float* mean_x  = (const float*)d_in[10];
    const float* var_x   = (const float*)d_in[11];
    float* out = (float*)d_out;

    float *zf, *xf;
    __half *zp16, *xp16, *wz16, *wx16;
    cudaGetSymbolAddress((void**)&zf, g_zf);
    cudaGetSymbolAddress((void**)&xf, g_xf);
    cudaGetSymbolAddress((void**)&zp16, g_zp);
    cudaGetSymbolAddress((void**)&xp16, g_xp);
    cudaGetSymbolAddress((void**)&wz16, g_wz);
    cudaGetSymbolAddress((void**)&wx16, g_wx);

    constexpr int SMEM_BYTES = 92160;

    static cudaStream_t s2 = nullptr;
    static cudaEvent_t e_fork = nullptr, e_join = nullptr;
    if (!s2) {
        cudaFuncSetAttribute(conv3x3_bn_wmma<14, 14, 16, 16>,
                             cudaFuncAttributeMaxDynamicSharedMemorySize, SMEM_BYTES);
        cudaFuncSetAttribute(conv3x3_bn_wmma<30, 30, 32, 32>,
                             cudaFuncAttributeMaxDynamicSharedMemorySize, SMEM_BYTES);
        cudaStreamCreateWithFlags(&s2, cudaStreamNonBlocking);
        cudaEventCreateWithFlags(&e_fork, cudaEventDisableTiming);
        cudaEventCreateWithFlags(&e_join, cudaEventDisableTiming);
    }

    // ---- fork: x-chain on side stream, z-chain on capture (null) stream ----
    cudaEventRecord(e_fork, 0);
    cudaStreamWaitEvent(s2, e_fork, 0);

    // x chain (big): pack x, pack wx, conv_x
    {
        int n4 = 64 * 256 * 32 * 32 / 4;
        pack_h_kernel<<<(n4 + 255) / 256, 256, 0, s2>>>(
            (const float4*)x, (uint2*)xp16, n4);
        n4 = 256 * 2304 / 4;
        pack_h_kernel<<<(n4 + 255) / 256, 256, 0, s2>>>(
            (const float4*)w_x, (uint2*)wx16, n4);
        conv3x3_bn_wmma<30, 30, 32, 32><<<dim3(900, 1), 256, SMEM_BYTES, s2>>>(
            xp16, wx16, gamma_x, beta_x, mean_x, var_x, xf);
    }
    cudaEventRecord(e_join, s2);

    // z chain (small) on the null stream
    {
        int n4 = 64 * 256 * 16 * 16 / 4;
        pack_h_kernel<<<(n4 + 255) / 256, 256>>>(
            (const float4*)z, (uint2*)zp16, n4);
        n4 = 256 * 2304 / 4;
        pack_h_kernel<<<(n4 + 255) / 256, 256>>>(
            (const float4*)w_z, (uint2*)wz16, n4);
        conv3x3_bn_wmma<14, 14, 16, 16><<<dim3(196, 1), 256, SMEM_BYTES>>>(
            zp16, wz16, gamma_z, beta_z, mean_z, var_z, zf);
    }

    // ---- join, then xcorr ----
    cudaStreamWaitEvent(0, e_join, 0);
    xcorr_kernel<<<1088, 256>>>(zf, xf, out);
}

// round 14
// speedup vs baseline: 1.4412x; 1.0026x over previous
#include <cuda_runtime.h>
#include <cuda_fp16.h>
#include <mma.h>
#include <cstdint>

using namespace nvcuda;

#define EPS 1e-5f

// Scratch (no cudaMalloc allowed). Feature maps stored TRANSPOSED: [spatial][bc]
__device__ __align__(16) float    g_zfT[196 * 16384];           // 12.8 MB
__device__ __align__(16) float    g_xfT[900 * 16384];           // 59 MB
__device__ __align__(16) __half   g_zp[64 * 256 * 16 * 16];     // fp16 z
__device__ __align__(16) __half   g_xp[64 * 256 * 32 * 32];     // fp16 x
__device__ __align__(16) __half   g_wz[256 * 2304];             // fp16 weights z
__device__ __align__(16) __half   g_wx[256 * 2304];             // fp16 weights x

__device__ __forceinline__ uint32_t smem_u32(const void* p) {
    uint32_t a;
    asm("{ .reg .u64 t; cvta.to.shared.u64 t, %1; cvt.u32.u64 %0, t; }"
        : "=r"(a) : "l"(p));
    return a;
}

#define CP_ASYNC16(dst, src) \
    asm volatile("cp.async.cg.shared.global [%0], [%1], 16;" \
        :: "r"(dst), "l"(src) : "memory")
#define CP_COMMIT() asm volatile("cp.async.commit_group;" ::: "memory")
#define CP_WAIT0()  asm volatile("cp.async.wait_group 0;" ::: "memory")

// ---- pack fp32 -> fp16 plane (inputs AND weights) ----
__global__ void pack_h_kernel(const float4* __restrict__ src,
                              uint2* __restrict__ dst, int n4)
{
    int i = blockIdx.x * blockDim.x + threadIdx.x;
    if (i >= n4) return;
    float4 v = __ldg(src + i);
    __half2 h01 = __floats2half2_rn(v.x, v.y);
    __half2 h23 = __floats2half2_rn(v.z, v.w);
    dst[i] = make_uint2(*reinterpret_cast<uint32_t*>(&h01),
                        *reinterpret_cast<uint32_t*>(&h23));
}

// ===========================================================================
// Implicit-GEMM 3x3 conv + fused BN, single-pass fp16 wmma.
// BM=256, BN=64, BK=64, 256 threads, warp tile 64x32, 2 CTAs/SM.
// Epilogue writes TRANSPOSED features out_T[s][bc] (fully coalesced, m=tid).
// ===========================================================================
template <int OH, int OW, int IH, int IW>
__global__ __launch_bounds__(256, 2)
void conv3x3_bn_wmma(const __half* __restrict__ xph,   // fp16 input [B,256,IH,IW]
                     const __half* __restrict__ whalf, // fp16 weights [256,2304]
                     const float* __restrict__ gamma,
                     const float* __restrict__ beta,
                     const float* __restrict__ mean,
                     const float* __restrict__ var,
                     float* __restrict__ outT)         // [OH*OW][64*256]
{
    constexpr int C = 256, K = C * 9;
    constexpr int BM = 256, BN = 64, BK = 64;
    constexpr int NCH = K / BK;                 // 36
    constexpr int OHW = OH * OW;
    constexpr int LDA = 72;                     // fp16 elems/row (144 B)
    constexpr int LDC = 68;
    constexpr uint32_t A_T = BM * LDA * 2;      // 36864
    constexpr uint32_t B_T = BN * LDA * 2;      // 9216
    constexpr uint32_t OF_B = 2 * A_T;          // 73728
    // total smem = 92160

    extern __shared__ char smem[];
    const uint32_t sbase = smem_u32(smem);

    const int tid = threadIdx.x;
    const int wid = tid >> 5;
    const int n0 = blockIdx.x * BN;
    const int wm = (wid >> 1) * 64;             // 4 m-warps
    const int wn = (wid & 1) * 32;              // 2 n-warps

    // --- A fill (cp.async): 8 chunks, chunk i: row r0+32i, 16B sub q ---
    const int r0 = tid >> 3;            // 0..31
    const int q  = tid & 7;             // 0..7
    const __half* whp = whalf + (size_t)r0 * K + q * 8;
    const uint32_t ad0 = (uint32_t)(r0 * 144 + q * 16);

    // --- B fill: one n, 16 k's per thread ---
    const int n_loc = tid & 63;
    const int koff  = (tid >> 6) * 16;  // 0,16,32,48
    const int n     = n0 + n_loc;
    const int b_    = n / OHW;
    const int rem   = n - b_ * OHW;
    const int ohh   = rem / OW;
    const int oww   = rem - ohh * OW;
    const __half* xb = xph + (size_t)b_ * C * IH * IW + (size_t)ohh * IW + oww;

    auto fillA = [&](int ch) {
        const uint32_t s = sbase + (uint32_t)(ch & 1) * A_T + ad0;
        const int ko = ch * BK;
#pragma unroll
        for (int i = 0; i < 8; i++)
            CP_ASYNC16(s + i * 4608u, whp + ko + (size_t)i * 32 * K);
    };

    auto ldgB = [&](int ch, uint32_t* v) {
        int kg = ch * BK + koff;
        int ci = kg / 9;
        int r9 = kg - ci * 9;
        int kh = r9 / 3;
        int kw = r9 - kh * 3;
#pragma unroll
        for (int j = 0; j < 16; j++) {
            v[j] = (uint32_t)__half_as_ushort(__ldg(xb + (ci * IH + kh) * IW + kw));
            kw++; if (kw == 3) { kw = 0; kh++; if (kh == 3) { kh = 0; ci++; } }
        }
    };
    auto stsB = [&](int ch, const uint32_t* v) {
        const int buf = ch & 1;
        uint32_t* db = (uint32_t*)(smem + OF_B + buf * B_T) + n_loc * 36 + (koff >> 1);
#pragma unroll
        for (int h = 0; h < 2; h++) {
            const uint32_t* s = v + h * 8;
            *reinterpret_cast<uint4*>(db + h * 4) = make_uint4(
                s[0] | (s[1] << 16), s[2] | (s[3] << 16),
                s[4] | (s[5] << 16), s[6] | (s[7] << 16));
        }
    };

    wmma::fragment<wmma::accumulator, 16, 16, 16, float> acc[4][2];
#pragma unroll
    for (int i = 0; i < 4; i++)
#pragma unroll
        for (int j = 0; j < 2; j++) wmma::fill_fragment(acc[i][j], 0.0f);

    // prologue: stage 0
    fillA(0);
    CP_COMMIT();
    {
        uint32_t v[16];
        ldgB(0, v);
        stsB(0, v);
    }

#pragma unroll 1
    for (int ch = 0; ch < NCH; ch++) {
        CP_WAIT0();
        __syncthreads();

        uint32_t v[16];
        const bool more = (ch + 1 < NCH);
        if (more) {
            fillA(ch + 1);
            CP_COMMIT();
            ldgB(ch + 1, v);           // LDGs in flight during MMA below
        }

        const int buf = ch & 1;
        const __half* sa = (const __half*)(smem + buf * A_T);
        const __half* sb = (const __half*)(smem + OF_B + buf * B_T);

#pragma unroll
        for (int ks = 0; ks < 4; ks++) {
            const int ko = ks * 16;
            wmma::fragment<wmma::matrix_b, 16, 16, 16, __half, wmma::col_major> b[2];
#pragma unroll
            for (int j = 0; j < 2; j++)
                wmma::load_matrix_sync(b[j], sb + (wn + j * 16) * LDA + ko, LDA);
#pragma unroll
            for (int i = 0; i < 4; i++) {
                wmma::fragment<wmma::matrix_a, 16, 16, 16, __half, wmma::row_major> a;
                wmma::load_matrix_sync(a, sa + (wm + i * 16) * LDA + ko, LDA);
#pragma unroll
                for (int j = 0; j < 2; j++)
                    wmma::mma_sync(acc[i][j], a, b[j], acc[i][j]);
            }
        }

        if (more) stsB(ch + 1, v);     // after MMA: LDG latency covered
    }

    // ---- epilogue: acc -> SMEM C tile -> BN -> TRANSPOSED coalesced store ----
    __syncthreads();
    float* ct = (float*)smem;                   // 256 x 68 fp32 = 69632 B
#pragma unroll
    for (int i = 0; i < 4; i++)
#pragma unroll
        for (int j = 0; j < 2; j++)
            wmma::store_matrix_sync(ct + (wm + i * 16) * LDC + wn + j * 16,
                                    acc[i][j], LDC, wmma::mem_row_major);
    __syncthreads();

    // m = tid (channel), loop over the 64 spatial positions; writes coalesced.
    {
        const float sc = __ldg(&gamma[tid]) * rsqrtf(__ldg(&var[tid]) + EPS);
        const float bi = __ldg(&beta[tid]) - __ldg(&mean[tid]) * sc;
#pragma unroll 1
        for (int it = 0; it < 64; it++) {
            const int nn = n0 + it;
            const int b2 = nn / OHW;
            const int s  = nn - b2 * OHW;
            outT[((size_t)s * 64 + b2) * 256 + tid] = ct[tid * LDC + it] * sc + bi;
        }
    }
}

// ===========================================================================
// Depthwise cross-correlation on transposed features.
// Thread (oh, bc) with bc FASTEST: all loads are 1-line coalesced (lanes =
// consecutive bc). 44 LDG + 238 FMA per p-iteration.
// ===========================================================================
__global__ __launch_bounds__(256)
void xcorr_kernel(const float* __restrict__ zfT,  // [196][16384]
                  const float* __restrict__ xfT,  // [900][16384]
                  float* __restrict__ out)        // [16384][17][17]
{
    const int g  = blockIdx.x * blockDim.x + threadIdx.x;   // < 17*16384 exact
    const int bc = g & 16383;
    const int oh = g >> 14;

    const float* zp = zfT + bc;
    const float* xp = xfT + bc;

    float acc[17];
#pragma unroll
    for (int j = 0; j < 17; j++) acc[j] = 0.f;

#pragma unroll 1
    for (int p = 0; p < 14; p++) {
        float xr[30];
#pragma unroll
        for (int t = 0; t < 30; t++)
            xr[t] = __ldg(xp + (size_t)((oh + p) * 30 + t) * 16384);
        float zr[14];
#pragma unroll
        for (int qq = 0; qq < 14; qq++)
            zr[qq] = __ldg(zp + (size_t)(p * 14 + qq) * 16384);
#pragma unroll
        for (int qq = 0; qq < 14; qq++) {
            float zv = zr[qq];
#pragma unroll
            for (int j = 0; j < 17; j++)
                acc[j] = fmaf(zv, xr[qq + j], acc[j]);
        }
    }

    float* op = out + (size_t)bc * 289 + oh * 17;
#pragma unroll
    for (int j = 0; j < 17; j++) op[j] = acc[j];
}

// ===========================================================================
extern "C" void kernel_launch(void* const* d_in, const int* in_sizes, int n_in,
                              void* d_out, int out_size)
{
    const float* z       = (const float*)d_in[0];
    const float* x       = (const float*)d_in[1];
    const float* w_z     = (const float*)d_in[2];
    const float* w_x     = (const float*)d_in[3];
    const float* gamma_z = (const float*)d_in[4];
    const float* beta_z  = (const float*)d_in[5];
    const float* mean_z  = (const float*)d_in[6];
    const float* var_z   = (const float*)d_in[7];
    const float* gamma_x = (const float*)d_in[8];
    const float* beta_x  = (const float*)d_in[9];
    const float* mean_x  = (const float*)d_in[10];
    const float* var_x   = (const float*)d_in[11];
    float* out = (float*)d_out;

    float *zfT, *xfT;
    __half *zp16, *xp16, *wz16, *wx16;
    cudaGetSymbolAddress((void**)&zfT, g_zfT);
    cudaGetSymbolAddress((void**)&xfT, g_xfT);
    cudaGetSymbolAddress((void**)&zp16, g_zp);
    cudaGetSymbolAddress((void**)&xp16, g_xp);
    cudaGetSymbolAddress((void**)&wz16, g_wz);
    cudaGetSymbolAddress((void**)&wx16, g_wx);

    constexpr int SMEM_BYTES = 92160;

    static cudaStream_t s2 = nullptr;
    static cudaEvent_t e_fork = nullptr, e_join = nullptr;
    if (!s2) {
        cudaFuncSetAttribute(conv3x3_bn_wmma<14, 14, 16, 16>,
                             cudaFuncAttributeMaxDynamicSharedMemorySize, SMEM_BYTES);
        cudaFuncSetAttribute(conv3x3_bn_wmma<30, 30, 32, 32>,
                             cudaFuncAttributeMaxDynamicSharedMemorySize, SMEM_BYTES);
        cudaStreamCreateWithFlags(&s2, cudaStreamNonBlocking);
        cudaEventCreateWithFlags(&e_fork, cudaEventDisableTiming);
        cudaEventCreateWithFlags(&e_join, cudaEventDisableTiming);
    }

    // ---- fork: x-chain on side stream, z-chain on capture (null) stream ----
    cudaEventRecord(e_fork, 0);
    cudaStreamWaitEvent(s2, e_fork, 0);

    // x chain (big): pack x, pack wx, conv_x
    {
        int n4 = 64 * 256 * 32 * 32 / 4;
        pack_h_kernel<<<(n4 + 255) / 256, 256, 0, s2>>>(
            (const float4*)x, (uint2*)xp16, n4);
        n4 = 256 * 2304 / 4;
        pack_h_kernel<<<(n4 + 255) / 256, 256, 0, s2>>>(
            (const float4*)w_x, (uint2*)wx16, n4);
        conv3x3_bn_wmma<30, 30, 32, 32><<<dim3(900, 1), 256, SMEM_BYTES, s2>>>(
            xp16, wx16, gamma_x, beta_x, mean_x, var_x, xfT);
    }
    cudaEventRecord(e_join, s2);

    // z chain (small) on the null stream
    {
        int n4 = 64 * 256 * 16 * 16 / 4;
        pack_h_kernel<<<(n4 + 255) / 256, 256>>>(
            (const float4*)z, (uint2*)zp16, n4);
        n4 = 256 * 2304 / 4;
        pack_h_kernel<<<(n4 + 255) / 256, 256>>>(
            (const float4*)w_z, (uint2*)wz16, n4);
        conv3x3_bn_wmma<14, 14, 16, 16><<<dim3(196, 1), 256, SMEM_BYTES>>>(
            zp16, wz16, gamma_z, beta_z, mean_z, var_z, zfT);
    }

    // ---- join, then xcorr (17*16384 threads = 1088 blocks) ----
    cudaStreamWaitEvent(0, e_join, 0);
    xcorr_kernel<<<1088, 256>>>(zfT, xfT, out);
}

// round 15
// speedup vs baseline: 1.4872x; 1.0319x over previous
#include <cuda_runtime.h>
#include <cuda_fp16.h>
#include <mma.h>
#include <cstdint>

using namespace nvcuda;

#define EPS 1e-5f

// Scratch (no cudaMalloc allowed). Feature maps TRANSPOSED: [spatial][bc]
__device__ __align__(16) float    g_zfT[196 * 16384];           // 12.8 MB
__device__ __align__(16) float    g_xfT[900 * 16384];           // 59 MB
__device__ __align__(16) __half   g_zp[64 * 16 * 16 * 256];     // fp16 z NHWC
__device__ __align__(16) __half   g_xp[64 * 32 * 32 * 256];     // fp16 x NHWC
__device__ __align__(16) __half   g_wz[256 * 2304];             // fp16 w_z tap-major
__device__ __align__(16) __half   g_wx[256 * 2304];             // fp16 w_x tap-major

__device__ __forceinline__ uint32_t smem_u32(const void* p) {
    uint32_t a;
    asm("{ .reg .u64 t; cvta.to.shared.u64 t, %1; cvt.u32.u64 %0, t; }"
        : "=r"(a) : "l"(p));
    return a;
}

#define CP_ASYNC16(dst, src) \
    asm volatile("cp.async.cg.shared.global [%0], [%1], 16;" \
        :: "r"(dst), "l"(src) : "memory")
#define CP_COMMIT() asm volatile("cp.async.commit_group;" ::: "memory")
#define CP_WAIT0()  asm volatile("cp.async.wait_group 0;" ::: "memory")

// ===========================================================================
// Pack input fp32 NCHW -> fp16 NHWC (smem-tiled transpose, conflict-free).
// One block per (b, h): reads [256 c][W w], writes [W w][256 c].
// ===========================================================================
template <int H, int W>
__global__ __launch_bounds__(256)
void pack_nhwc(const float* __restrict__ src, __half* __restrict__ dst)
{
    __shared__ __half sm[32 * 258];   // [w][c], fp16 stride 258 (bank-safe)
    const int bh   = blockIdx.x;      // b*H + h
    const int b    = bh / H;
    const int h    = bh - b * H;
    const int tid  = threadIdx.x;
    const int wid  = tid >> 5;
    const int lane = tid & 31;

    // read: warp wid covers channels c = wid, wid+8, ... (coalesced along w)
#pragma unroll 4
    for (int c = wid; c < 256; c += 8) {
        if (lane < W) {
            float v = __ldg(src + (((size_t)b * 256 + c) * H + h) * W + lane);
            sm[lane * 258 + c] = __float2half_rn(v);
        }
    }
    __syncthreads();

    // write: thread t -> w = t>>3, c0 = (t&7)*32; 64 B per thread, coalesced
    const int w  = tid >> 3;
    const int c0 = (tid & 7) << 5;
    if (w < W) {
        __half* dp = dst + (((size_t)bh) * W + w) * 256 + c0;
        uint32_t tmp[16];
#pragma unroll
        for (int i = 0; i < 16; i++) {
            __half2 hh = __halves2half2(sm[w * 258 + c0 + 2 * i],
                                        sm[w * 258 + c0 + 2 * i + 1]);
            tmp[i] = *reinterpret_cast<uint32_t*>(&hh);
        }
#pragma unroll
        for (int i = 0; i < 4; i++)
            reinterpret_cast<uint4*>(dp)[i] =
                make_uint4(tmp[4 * i], tmp[4 * i + 1], tmp[4 * i + 2], tmp[4 * i + 3]);
    }
}

// ---- pack weights fp32 [m][ci*9+r9] -> fp16 tap-major [m][r9*256+ci] ----
__global__ void pack_wT(const float* __restrict__ src, __half* __restrict__ dst)
{
    int i = blockIdx.x * blockDim.x + threadIdx.x;   // over 256*2304
    if (i >= 256 * 2304) return;
    int m  = i / 2304;
    int kp = i - m * 2304;
    int r9 = kp >> 8;
    int ci = kp & 255;
    dst[i] = __float2half_rn(__ldg(src + m * 2304 + ci * 9 + r9));
}

// ===========================================================================
// Implicit-GEMM 3x3 conv + fused BN, single-pass fp16 wmma, NHWC B path.
// k' = tap*256 + ci: each BK=64 chunk = one tap + 64 contiguous channels ->
// B fill = 2x LDG.128 + 2x STS.128 per thread per iteration.
// BM=256, BN=64, BK=64, 256 threads, warp tile 64x32, 2 CTAs/SM.
// ===========================================================================
template <int OH, int OW, int IH, int IW>
__global__ __launch_bounds__(256, 2)
void conv3x3_bn_wmma(const __half* __restrict__ xph,   // fp16 NHWC [B,IH,IW,256]
                     const __half* __restrict__ whalf, // fp16 [256][2304] tap-major
                     const float* __restrict__ gamma,
                     const float* __restrict__ beta,
                     const float* __restrict__ mean,
                     const float* __restrict__ var,
                     float* __restrict__ outT)         // [OH*OW][64*256]
{
    constexpr int C = 256, K = C * 9;
    constexpr int BM = 256, BN = 64, BK = 64;
    constexpr int NCH = K / BK;                 // 36 (4 chunks per tap)
    constexpr int OHW = OH * OW;
    constexpr int LDA = 72;                     // fp16 elems/row (144 B)
    constexpr int LDC = 68;
    constexpr uint32_t A_T = BM * LDA * 2;      // 36864
    constexpr uint32_t B_T = BN * LDA * 2;      // 9216
    constexpr uint32_t OF_B = 2 * A_T;          // 73728
    // total smem = 92160

    extern __shared__ char smem[];
    const uint32_t sbase = smem_u32(smem);

    const int tid = threadIdx.x;
    const int wid = tid >> 5;
    const int n0 = blockIdx.x * BN;
    const int wm = (wid >> 1) * 64;             // 4 m-warps
    const int wn = (wid & 1) * 32;              // 2 n-warps

    // --- A fill (cp.async): 8 chunks, chunk i: row r0+32i, 16B sub q ---
    const int r0 = tid >> 3;            // 0..31
    const int q  = tid & 7;             // 0..7
    const __half* whp = whalf + (size_t)r0 * K + q * 8;
    const uint32_t ad0 = (uint32_t)(r0 * 144 + q * 16);

    // --- B fill: one n, 16 contiguous channels per thread ---
    const int n_loc = tid & 63;
    const int koff  = (tid >> 6) * 16;  // 0,16,32,48 (channel sub-offset)
    const int n     = n0 + n_loc;
    const int b_    = n / OHW;
    const int rem   = n - b_ * OHW;
    const int ohh   = rem / OW;
    const int oww   = rem - ohh * OW;
    const __half* xbT = xph + (size_t)b_ * IH * IW * 256;

    auto fillA = [&](int ch) {
        const uint32_t s = sbase + (uint32_t)(ch & 1) * A_T + ad0;
        const int ko = ch * BK;
#pragma unroll
        for (int i = 0; i < 8; i++)
            CP_ASYNC16(s + i * 4608u, whp + ko + (size_t)i * 32 * K);
    };

    auto ldgB = [&](int ch, uint4* v) {
        const int r9 = ch >> 2;                       // tap 0..8
        const int kh = r9 / 3, kw = r9 - kh * 3;
        const int ci0 = ((ch & 3) << 6) + koff;       // 0..255, 16B-aligned
        const __half* p = xbT +
            ((size_t)((ohh + kh) * IW + (oww + kw))) * 256 + ci0;
        v[0] = __ldg(reinterpret_cast<const uint4*>(p));
        v[1] = __ldg(reinterpret_cast<const uint4*>(p + 8));
    };
    auto stsB = [&](int ch, const uint4* v) {
        const int buf = ch & 1;
        uint4* db = reinterpret_cast<uint4*>(
            (uint32_t*)(smem + OF_B + buf * B_T) + n_loc * 36 + (koff >> 1));
        db[0] = v[0];
        db[1] = v[1];
    };

    wmma::fragment<wmma::accumulator, 16, 16, 16, float> acc[4][2];
#pragma unroll
    for (int i = 0; i < 4; i++)
#pragma unroll
        for (int j = 0; j < 2; j++) wmma::fill_fragment(acc[i][j], 0.0f);

    // prologue: stage 0
    fillA(0);
    CP_COMMIT();
    {
        uint4 v[2];
        ldgB(0, v);
        stsB(0, v);
    }

#pragma unroll 1
    for (int ch = 0; ch < NCH; ch++) {
        CP_WAIT0();
        __syncthreads();

        uint4 v[2];
        const bool more = (ch + 1 < NCH);
        if (more) {
            fillA(ch + 1);
            CP_COMMIT();
            ldgB(ch + 1, v);           // LDGs in flight during MMA below
        }

        const int buf = ch & 1;
        const __half* sa = (const __half*)(smem + buf * A_T);
        const __half* sb = (const __half*)(smem + OF_B + buf * B_T);

#pragma unroll
        for (int ks = 0; ks < 4; ks++) {
            const int ko = ks * 16;
            wmma::fragment<wmma::matrix_b, 16, 16, 16, __half, wmma::col_major> b[2];
#pragma unroll
            for (int j = 0; j < 2; j++)
                wmma::load_matrix_sync(b[j], sb + (wn + j * 16) * LDA + ko, LDA);
#pragma unroll
            for (int i = 0; i < 4; i++) {
                wmma::fragment<wmma::matrix_a, 16, 16, 16, __half, wmma::row_major> a;
                wmma::load_matrix_sync(a, sa + (wm + i * 16) * LDA + ko, LDA);
#pragma unroll
                for (int j = 0; j < 2; j++)
                    wmma::mma_sync(acc[i][j], a, b[j], acc[i][j]);
            }
        }

        if (more) stsB(ch + 1, v);     // after MMA: LDG latency covered
    }

    // ---- epilogue: acc -> SMEM C tile -> BN -> TRANSPOSED coalesced store ----
    __syncthreads();
    float* ct = (float*)smem;                   // 256 x 68 fp32 = 69632 B
#pragma unroll
    for (int i = 0; i < 4; i++)
#pragma unroll
        for (int j = 0; j < 2; j++)
            wmma::store_matrix_sync(ct + (wm + i * 16) * LDC + wn + j * 16,
                                    acc[i][j], LDC, wmma::mem_row_major);
    __syncthreads();

    // m = tid (channel); 64 spatial positions; fully coalesced stores.
    {
        const float sc = __ldg(&gamma[tid]) * rsqrtf(__ldg(&var[tid]) + EPS);
        const float bi = __ldg(&beta[tid]) - __ldg(&mean[tid]) * sc;
#pragma unroll 1
        for (int it = 0; it < 64; it++) {
            const int nn = n0 + it;
            const int b2 = nn / OHW;
            const int s  = nn - b2 * OHW;
            outT[((size_t)s * 64 + b2) * 256 + tid] = ct[tid * LDC + it] * sc + bi;
        }
    }
}

// ===========================================================================
// Depthwise cross-correlation on transposed features (bc fastest, coalesced).
// ===========================================================================
__global__ __launch_bounds__(256)
void xcorr_kernel(const float* __restrict__ zfT,  // [196][16384]
                  const float* __restrict__ xfT,  // [900][16384]
                  float* __restrict__ out)        // [16384][17][17]
{
    const int g  = blockIdx.x * blockDim.x + threadIdx.x;
    const int bc = g & 16383;
    const int oh = g >> 14;

    const float* zp = zfT + bc;
    const float* xp = xfT + bc;

    float acc[17];
#pragma unroll
    for (int j = 0; j < 17; j++) acc[j] = 0.f;

#pragma unroll 1
    for (int p = 0; p < 14; p++) {
        float xr[30];
#pragma unroll
        for (int t = 0; t < 30; t++)
            xr[t] = __ldg(xp + (size_t)((oh + p) * 30 + t) * 16384);
        float zr[14];
#pragma unroll
        for (int qq = 0; qq < 14; qq++)
            zr[qq] = __ldg(zp + (size_t)(p * 14 + qq) * 16384);
#pragma unroll
        for (int qq = 0; qq < 14; qq++) {
            float zv = zr[qq];
#pragma unroll
            for (int j = 0; j < 17; j++)
                acc[j] = fmaf(zv, xr[qq + j], acc[j]);
        }
    }

    float* op = out + (size_t)bc * 289 + oh * 17;
#pragma unroll
    for (int j = 0; j < 17; j++) op[j] = acc[j];
}

// ===========================================================================
extern "C" void kernel_launch(void* const* d_in, const int* in_sizes, int n_in,
                              void* d_out, int out_size)
{
    const float* z       = (const float*)d_in[0];
    const float* x       = (const float*)d_in[1];
    const float* w_z     = (const float*)d_in[2];
    const float* w_x     = (const float*)d_in[3];
    const float* gamma_z = (const float*)d_in[4];
    const float* beta_z  = (const float*)d_in[5];
    const float* mean_z  = (const float*)d_in[6];
    const float* var_z   = (const float*)d_in[7];
    const float* gamma_x = (const float*)d_in[8];
    const float* beta_x  = (const float*)d_in[9];
    const float* mean_x  = (const float*)d_in[10];
    const float* var_x   = (const float*)d_in[11];
    float* out = (float*)d_out;

    float *zfT, *xfT;
    __half *zp16, *xp16, *wz16, *wx16;
    cudaGetSymbolAddress((void**)&zfT, g_zfT);
    cudaGetSymbolAddress((void**)&xfT, g_xfT);
    cudaGetSymbolAddress((void**)&zp16, g_zp);
    cudaGetSymbolAddress((void**)&xp16, g_xp);
    cudaGetSymbolAddress((void**)&wz16, g_wz);
    cudaGetSymbolAddress((void**)&wx16, g_wx);

    constexpr int SMEM_BYTES = 92160;

    static cudaStream_t s2 = nullptr;
    static cudaEvent_t e_fork = nullptr, e_join = nullptr;
    if (!s2) {
        cudaFuncSetAttribute(conv3x3_bn_wmma<14, 14, 16, 16>,
                             cudaFuncAttributeMaxDynamicSharedMemorySize, SMEM_BYTES);
        cudaFuncSetAttribute(conv3x3_bn_wmma<30, 30, 32, 32>,
                             cudaFuncAttributeMaxDynamicSharedMemorySize, SMEM_BYTES);
        cudaStreamCreateWithFlags(&s2, cudaStreamNonBlocking);
        cudaEventCreateWithFlags(&e_fork, cudaEventDisableTiming);
        cudaEventCreateWithFlags(&e_join, cudaEventDisableTiming);
    }

    // ---- fork: x-chain on side stream, z-chain on capture (null) stream ----
    cudaEventRecord(e_fork, 0);
    cudaStreamWaitEvent(s2, e_fork, 0);

    // x chain (big): NHWC pack x, tap-major pack wx, conv_x
    {
        pack_nhwc<32, 32><<<64 * 32, 256, 0, s2>>>(x, xp16);
        pack_wT<<<(256 * 2304 + 255) / 256, 256, 0, s2>>>(w_x, wx16);
        conv3x3_bn_wmma<30, 30, 32, 32><<<dim3(900, 1), 256, SMEM_BYTES, s2>>>(
            xp16, wx16, gamma_x, beta_x, mean_x, var_x, xfT);
    }
    cudaEventRecord(e_join, s2);

    // z chain (small) on the null stream
    {
        pack_nhwc<16, 16><<<64 * 16, 256>>>(z, zp16);
        pack_wT<<<(256 * 2304 + 255) / 256, 256>>>(w_z, wz16);
        conv3x3_bn_wmma<14, 14, 16, 16><<<dim3(196, 1), 256, SMEM_BYTES>>>(
            zp16, wz16, gamma_z, beta_z, mean_z, var_z, zfT);
    }

    // ---- join, then xcorr (17*16384 threads = 1088 blocks) ----
    cudaStreamWaitEvent(0, e_join, 0);
    xcorr_kernel<<<1088, 256>>>(zfT, xfT, out);
}

// round 16
// speedup vs baseline: 1.4903x; 1.0021x over previous
#include <cuda_runtime.h>
#include <cuda_fp16.h>
#include <mma.h>
#include <cstdint>

using namespace nvcuda;

#define EPS 1e-5f

// Scratch (no cudaMalloc allowed). Feature maps TRANSPOSED: [spatial][bc]
__device__ __align__(16) float    g_zfT[196 * 16384];           // 12.8 MB
__device__ __align__(16) float    g_xfT[900 * 16384];           // 59 MB
__device__ __align__(16) __half   g_zp[64 * 16 * 16 * 256];     // fp16 z NHWC
__device__ __align__(16) __half   g_xp[64 * 32 * 32 * 256];     // fp16 x NHWC
__device__ __align__(16) __half   g_wz[256 * 2304];             // fp16 w_z tap-major
__device__ __align__(16) __half   g_wx[256 * 2304];             // fp16 w_x tap-major

__device__ __forceinline__ uint32_t smem_u32(const void* p) {
    uint32_t a;
    asm("{ .reg .u64 t; cvta.to.shared.u64 t, %1; cvt.u32.u64 %0, t; }"
        : "=r"(a) : "l"(p));
    return a;
}

#define CP_ASYNC16(dst, src) \
    asm volatile("cp.async.cg.shared.global [%0], [%1], 16;" \
        :: "r"(dst), "l"(src) : "memory")
#define CP_COMMIT() asm volatile("cp.async.commit_group;" ::: "memory")
#define CP_WAIT0()  asm volatile("cp.async.wait_group 0;" ::: "memory")

// ===========================================================================
// Pack input fp32 NCHW -> fp16 NHWC (smem-tiled transpose, conflict-free).
// ===========================================================================
template <int H, int W>
__global__ __launch_bounds__(256)
void pack_nhwc(const float* __restrict__ src, __half* __restrict__ dst)
{
    __shared__ __half sm[32 * 258];   // [w][c], fp16 stride 258 (bank-safe)
    const int bh   = blockIdx.x;      // b*H + h
    const int b    = bh / H;
    const int h    = bh - b * H;
    const int tid  = threadIdx.x;
    const int wid  = tid >> 5;
    const int lane = tid & 31;

#pragma unroll 4
    for (int c = wid; c < 256; c += 8) {
        if (lane < W) {
            float v = __ldg(src + (((size_t)b * 256 + c) * H + h) * W + lane);
            sm[lane * 258 + c] = __float2half_rn(v);
        }
    }
    __syncthreads();

    const int w  = tid >> 3;
    const int c0 = (tid & 7) << 5;
    if (w < W) {
        __half* dp = dst + (((size_t)bh) * W + w) * 256 + c0;
        uint32_t tmp[16];
#pragma unroll
        for (int i = 0; i < 16; i++) {
            __half2 hh = __halves2half2(sm[w * 258 + c0 + 2 * i],
                                        sm[w * 258 + c0 + 2 * i + 1]);
            tmp[i] = *reinterpret_cast<uint32_t*>(&hh);
        }
#pragma unroll
        for (int i = 0; i < 4; i++)
            reinterpret_cast<uint4*>(dp)[i] =
                make_uint4(tmp[4 * i], tmp[4 * i + 1], tmp[4 * i + 2], tmp[4 * i + 3]);
    }
}

// ---- pack weights fp32 [m][ci*9+r9] -> fp16 tap-major [m][r9*256+ci] ----
__global__ void pack_wT(const float* __restrict__ src, __half* __restrict__ dst)
{
    int i = blockIdx.x * blockDim.x + threadIdx.x;   // over 256*2304
    if (i >= 256 * 2304) return;
    int m  = i / 2304;
    int kp = i - m * 2304;
    int r9 = kp >> 8;
    int ci = kp & 255;
    dst[i] = __float2half_rn(__ldg(src + m * 2304 + ci * 9 + r9));
}

// ===========================================================================
// Implicit-GEMM 3x3 conv + fused BN, single-pass fp16 wmma, NHWC B path.
// BOTH operand fills are cp.async (zero register staging, no LDG->STS chain).
// BM=256, BN=64, BK=64, 256 threads, warp tile 64x32, 2 CTAs/SM.
// ===========================================================================
template <int OH, int OW, int IH, int IW>
__global__ __launch_bounds__(256, 2)
void conv3x3_bn_wmma(const __half* __restrict__ xph,   // fp16 NHWC [B,IH,IW,256]
                     const __half* __restrict__ whalf, // fp16 [256][2304] tap-major
                     const float* __restrict__ gamma,
                     const float* __restrict__ beta,
                     const float* __restrict__ mean,
                     const float* __restrict__ var,
                     float* __restrict__ outT)         // [OH*OW][64*256]
{
    constexpr int C = 256, K = C * 9;
    constexpr int BM = 256, BN = 64, BK = 64;
    constexpr int NCH = K / BK;                 // 36 (4 chunks per tap)
    constexpr int OHW = OH * OW;
    constexpr int LDA = 72;                     // fp16 elems/row (144 B)
    constexpr int LDC = 68;
    constexpr uint32_t A_T = BM * LDA * 2;      // 36864
    constexpr uint32_t B_T = BN * LDA * 2;      // 9216
    constexpr uint32_t OF_B = 2 * A_T;          // 73728
    // total smem = 92160

    extern __shared__ char smem[];
    const uint32_t sbase = smem_u32(smem);

    const int tid = threadIdx.x;
    const int wid = tid >> 5;
    const int n0 = blockIdx.x * BN;
    const int wm = (wid >> 1) * 64;             // 4 m-warps
    const int wn = (wid & 1) * 32;              // 2 n-warps

    // --- A fill (cp.async): 8 chunks, chunk i: row r0+32i, 16B sub q ---
    const int r0 = tid >> 3;            // 0..31
    const int q  = tid & 7;             // 0..7
    const __half* whp = whalf + (size_t)r0 * K + q * 8;
    const uint32_t ad0 = (uint32_t)(r0 * 144 + q * 16);

    // --- B fill (cp.async): one n, 16 contiguous channels per thread ---
    const int n_loc = tid & 63;
    const int koff  = (tid >> 6) * 16;  // 0,16,32,48 (channel sub-offset)
    const int n     = n0 + n_loc;
    const int b_    = n / OHW;
    const int rem   = n - b_ * OHW;
    const int ohh   = rem / OW;
    const int oww   = rem - ohh * OW;
    const __half* xbT = xph + (size_t)b_ * IH * IW * 256;
    const uint32_t bd0 = (uint32_t)(n_loc * 144 + koff * 2);   // smem byte off

    auto fillA = [&](int ch) {
        const uint32_t s = sbase + (uint32_t)(ch & 1) * A_T + ad0;
        const int ko = ch * BK;
#pragma unroll
        for (int i = 0; i < 8; i++)
            CP_ASYNC16(s + i * 4608u, whp + ko + (size_t)i * 32 * K);
    };

    auto fillB = [&](int ch) {
        const int r9 = ch >> 2;                       // tap 0..8
        const int kh = r9 / 3, kw = r9 - kh * 3;
        const int ci0 = ((ch & 3) << 6) + koff;       // 0..255
        const __half* p = xbT +
            ((size_t)((ohh + kh) * IW + (oww + kw))) * 256 + ci0;
        const uint32_t s = sbase + OF_B + (uint32_t)(ch & 1) * B_T + bd0;
        CP_ASYNC16(s, p);
        CP_ASYNC16(s + 16u, p + 8);
    };

    wmma::fragment<wmma::accumulator, 16, 16, 16, float> acc[4][2];
#pragma unroll
    for (int i = 0; i < 4; i++)
#pragma unroll
        for (int j = 0; j < 2; j++) wmma::fill_fragment(acc[i][j], 0.0f);

    // prologue: stage 0
    fillA(0);
    fillB(0);
    CP_COMMIT();

#pragma unroll 1
    for (int ch = 0; ch < NCH; ch++) {
        CP_WAIT0();
        __syncthreads();

        if (ch + 1 < NCH) {
            fillA(ch + 1);
            fillB(ch + 1);
            CP_COMMIT();               // lands during the MMA section below
        }

        const int buf = ch & 1;
        const __half* sa = (const __half*)(smem + buf * A_T);
        const __half* sb = (const __half*)(smem + OF_B + buf * B_T);

#pragma unroll
        for (int ks = 0; ks < 4; ks++) {
            const int ko = ks * 16;
            wmma::fragment<wmma::matrix_b, 16, 16, 16, __half, wmma::col_major> b[2];
#pragma unroll
            for (int j = 0; j < 2; j++)
                wmma::load_matrix_sync(b[j], sb + (wn + j * 16) * LDA + ko, LDA);
#pragma unroll
            for (int i = 0; i < 4; i++) {
                wmma::fragment<wmma::matrix_a, 16, 16, 16, __half, wmma::row_major> a;
                wmma::load_matrix_sync(a, sa + (wm + i * 16) * LDA + ko, LDA);
#pragma unroll
                for (int j = 0; j < 2; j++)
                    wmma::mma_sync(acc[i][j], a, b[j], acc[i][j]);
            }
        }
    }

    // ---- epilogue: acc -> SMEM C tile -> BN -> TRANSPOSED coalesced store ----
    __syncthreads();
    float* ct = (float*)smem;                   // 256 x 68 fp32 = 69632 B
#pragma unroll
    for (int i = 0; i < 4; i++)
#pragma unroll
        for (int j = 0; j < 2; j++)
            wmma::store_matrix_sync(ct + (wm + i * 16) * LDC + wn + j * 16,
                                    acc[i][j], LDC, wmma::mem_row_major);
    __syncthreads();

    // m = tid (channel); 64 spatial positions; fully coalesced stores.
    {
        const float sc = __ldg(&gamma[tid]) * rsqrtf(__ldg(&var[tid]) + EPS);
        const float bi = __ldg(&beta[tid]) - __ldg(&mean[tid]) * sc;
#pragma unroll 1
        for (int it = 0; it < 64; it++) {
            const int nn = n0 + it;
            const int b2 = nn / OHW;
            const int s  = nn - b2 * OHW;
            outT[((size_t)s * 64 + b2) * 256 + tid] = ct[tid * LDC + it] * sc + bi;
        }
    }
}

// ===========================================================================
// Depthwise cross-correlation on transposed features (bc fastest, coalesced).
// ===========================================================================
__global__ __launch_bounds__(256)
void xcorr_kernel(const float* __restrict__ zfT,  // [196][16384]
                  const float* __restrict__ xfT,  // [900][16384]
                  float* __restrict__ out)        // [16384][17][17]
{
    const int g  = blockIdx.x * blockDim.x + threadIdx.x;
    const int bc = g & 16383;
    const int oh = g >> 14;

    const float* zp = zfT + bc;
    const float* xp = xfT + bc;

    float acc[17];
#pragma unroll
    for (int j = 0; j < 17; j++) acc[j] = 0.f;

#pragma unroll 1
    for (int p = 0; p < 14; p++) {
        float xr[30];
#pragma unroll
        for (int t = 0; t < 30; t++)
            xr[t] = __ldg(xp + (size_t)((oh + p) * 30 + t) * 16384);
        float zr[14];
#pragma unroll
        for (int qq = 0; qq < 14; qq++)
            zr[qq] = __ldg(zp + (size_t)(p * 14 + qq) * 16384);
#pragma unroll
        for (int qq = 0; qq < 14; qq++) {
            float zv = zr[qq];
#pragma unroll
            for (int j = 0; j < 17; j++)
                acc[j] = fmaf(zv, xr[qq + j], acc[j]);
        }
    }

    float* op = out + (size_t)bc * 289 + oh * 17;
#pragma unroll
    for (int j = 0; j < 17; j++) op[j] = acc[j];
}

// ===========================================================================
extern "C" void kernel_launch(void* const* d_in, const int* in_sizes, int n_in,
                              void* d_out, int out_size)
{
    const float* z       = (const float*)d_in[0];
    const float* x       = (const float*)d_in[1];
    const float* w_z     = (const float*)d_in[2];
    const float* w_x     = (const float*)d_in[3];
    const float* gamma_z = (const float*)d_in[4];
    const float* beta_z  = (const float*)d_in[5];
    const float* mean_z  = (const float*)d_in[6];
    const float* var_z   = (const float*)d_in[7];
    const float* gamma_x = (const float*)d_in[8];
    const float* beta_x  = (const float*)d_in[9];
    const float* mean_x  = (const float*)d_in[10];
    const float* var_x   = (const float*)d_in[11];
    float* out = (float*)d_out;

    float *zfT, *xfT;
    __half *zp16, *xp16, *wz16, *wx16;
    cudaGetSymbolAddress((void**)&zfT, g_zfT);
    cudaGetSymbolAddress((void**)&xfT, g_xfT);
    cudaGetSymbolAddress((void**)&zp16, g_zp);
    cudaGetSymbolAddress((void**)&xp16, g_xp);
    cudaGetSymbolAddress((void**)&wz16, g_wz);
    cudaGetSymbolAddress((void**)&wx16, g_wx);

    constexpr int SMEM_BYTES = 92160;

    static cudaStream_t s2 = nullptr;
    static cudaEvent_t e_fork = nullptr, e_join = nullptr;
    if (!s2) {
        cudaFuncSetAttribute(conv3x3_bn_wmma<14, 14, 16, 16>,
                             cudaFuncAttributeMaxDynamicSharedMemorySize, SMEM_BYTES);
        cudaFuncSetAttribute(conv3x3_bn_wmma<30, 30, 32, 32>,
                             cudaFuncAttributeMaxDynamicSharedMemorySize, SMEM_BYTES);
        cudaStreamCreateWithFlags(&s2, cudaStreamNonBlocking);
        cudaEventCreateWithFlags(&e_fork, cudaEventDisableTiming);
        cudaEventCreateWithFlags(&e_join, cudaEventDisableTiming);
    }

    // ---- fork: x-chain on side stream, z-chain on capture (null) stream ----
    cudaEventRecord(e_fork, 0);
    cudaStreamWaitEvent(s2, e_fork, 0);

    // x chain (big): NHWC pack x, tap-major pack wx, conv_x
    {
        pack_nhwc<32, 32><<<64 * 32, 256, 0, s2>>>(x, xp16);
        pack_wT<<<(256 * 2304 + 255) / 256, 256, 0, s2>>>(w_x, wx16);
        conv3x3_bn_wmma<30, 30, 32, 32><<<dim3(900, 1), 256, SMEM_BYTES, s2>>>(
            xp16, wx16, gamma_x, beta_x, mean_x, var_x, xfT);
    }
    cudaEventRecord(e_join, s2);

    // z chain (small) on the null stream
    {
        pack_nhwc<16, 16><<<64 * 16, 256>>>(z, zp16);
        pack_wT<<<(256 * 2304 + 255) / 256, 256>>>(w_z, wz16);
        conv3x3_bn_wmma<14, 14, 16, 16><<<dim3(196, 1), 256, SMEM_BYTES>>>(
            zp16, wz16, gamma_z, beta_z, mean_z, var_z, zfT);
    }

    // ---- join, then xcorr (17*16384 threads = 1088 blocks) ----
    cudaStreamWaitEvent(0, e_join, 0);
    xcorr_kernel<<<1088, 256>>>(zfT, xfT, out);
}